// round 15
// baseline (speedup 1.0000x reference)
#include <cuda_runtime.h>
#include <cuda_bf16.h>

#define X_CH   256
#define Y_CH   512
#define DIM    128
#define NHEAD  4
#define HD     32
#define HWX    4096
#define HWY    1024
#define BATCH  2
#define GAMMA  0.17677669529663687f
#define GAMMA_L2E (0.17677669529663687f * 1.4426950408889634f)

typedef __nv_bfloat16 bf16;

// ---------------- scratch (device globals; no allocation) ----------------
static __device__ __align__(16) bf16 g_qxh[BATCH*NHEAD*HWX*HD], g_qxl[BATCH*NHEAD*HWX*HD];
static __device__ __align__(16) bf16 g_kxh[BATCH*NHEAD*HWX*HD], g_kxl[BATCH*NHEAD*HWX*HD];
static __device__ __align__(16) bf16 g_vxh[BATCH*NHEAD*HWX*HD], g_vxl[BATCH*NHEAD*HWX*HD];
static __device__ __align__(16) bf16 g_qyh[BATCH*NHEAD*HWY*HD], g_qyl[BATCH*NHEAD*HWY*HD];
static __device__ __align__(16) bf16 g_kyh[BATCH*NHEAD*HWY*HD], g_kyl[BATCH*NHEAD*HWY*HD];
static __device__ __align__(16) bf16 g_vyh[BATCH*NHEAD*HWY*HD], g_vyl[BATCH*NHEAD*HWY*HD];
// attention out, split bf16, TRANSPOSED [b, c=h*32+d, q]
static __device__ __align__(16) bf16 g_axh[BATCH*DIM*HWX], g_axl[BATCH*DIM*HWX];
static __device__ __align__(16) bf16 g_ayh[BATCH*DIM*HWY], g_ayl[BATCH*DIM*HWY];
// pre-split weights [M][K] and inputs [B][C][N]
static __device__ __align__(16) bf16 g_wxqh[384*X_CH], g_wxql[384*X_CH];
static __device__ __align__(16) bf16 g_wyqh[384*Y_CH], g_wyql[384*Y_CH];
static __device__ __align__(16) bf16 g_wpxh[X_CH*DIM], g_wpxl[X_CH*DIM];
static __device__ __align__(16) bf16 g_wpyh[Y_CH*DIM], g_wpyl[Y_CH*DIM];
static __device__ __align__(16) bf16 g_xsh[BATCH*X_CH*HWX], g_xsl[BATCH*X_CH*HWX];
static __device__ __align__(16) bf16 g_ysh[BATCH*Y_CH*HWY], g_ysl[BATCH*Y_CH*HWY];
// split-K partials for dir1
static __device__ __align__(16) float  g_pacc[4*BATCH*NHEAD*HWY*HD];
static __device__ __align__(16) float2 g_pml[4*BATCH*NHEAD*HWY];

__device__ __forceinline__ void bsplit(float v, bf16& h, bf16& l) {
    h = __float2bfloat16(v);
    l = __float2bfloat16(v - __bfloat162float(h));
}
__device__ __forceinline__ unsigned pack2(bf16 a, bf16 b) {
    return (unsigned)__bfloat16_as_ushort(a) | ((unsigned)__bfloat16_as_ushort(b) << 16);
}
__device__ __forceinline__ void psplit2(float x0, float x1, unsigned& ph, unsigned& pl) {
    unsigned h;
    asm("cvt.rn.bf16x2.f32 %0, %1, %2;" : "=r"(h) : "f"(x1), "f"(x0));
    float h0 = __uint_as_float(h << 16);
    float h1 = __uint_as_float(h & 0xffff0000u);
    float e0 = x0 - h0, e1 = x1 - h1;
    asm("cvt.rn.bf16x2.f32 %0, %1, %2;" : "=r"(pl) : "f"(e1), "f"(e0));
    ph = h;
}

// ---------------- prep: split all 4 weight matrices (validated) -----------
__global__ void __launch_bounds__(256) split_w_kernel(
    const float* __restrict__ s0, const float* __restrict__ s1,
    const float* __restrict__ s2, const float* __restrict__ s3)
{
    int e = (blockIdx.x * 256 + threadIdx.x) * 4;
    const float* s; bf16 *dh, *dl;
    if (e < 98304)       { s = s0; dh = g_wxqh; dl = g_wxql; }
    else if (e < 294912) { e -= 98304;  s = s1; dh = g_wyqh; dl = g_wyql; }
    else if (e < 327680) { e -= 294912; s = s2; dh = g_wpxh; dl = g_wpxl; }
    else                 { e -= 327680; s = s3; dh = g_wpyh; dl = g_wpyl; }
    float4 v = *(const float4*)(s + e);
    bf16 h0,l0,h1,l1,h2,l2,h3,l3;
    bsplit(v.x,h0,l0); bsplit(v.y,h1,l1); bsplit(v.z,h2,l2); bsplit(v.w,h3,l3);
    *(uint2*)(dh + e) = make_uint2(pack2(h0,h1), pack2(h2,h3));
    *(uint2*)(dl + e) = make_uint2(pack2(l0,l1), pack2(l2,l3));
}

// ---------------- prep: split inputs elementwise (validated) ----------
__global__ void __launch_bounds__(256) presplit_x_kernel(
    const float* __restrict__ x, const float* __restrict__ y)
{
    int e = (blockIdx.x * 256 + threadIdx.x) * 4;
    const float* s; bf16 *dh, *dl;
    if (e < BATCH*X_CH*HWX) { s = x; dh = g_xsh; dl = g_xsl; }
    else { e -= BATCH*X_CH*HWX; s = y; dh = g_ysh; dl = g_ysl; }
    float4 v = *(const float4*)(s + e);
    bf16 h0,l0,h1,l1,h2,l2,h3,l3;
    bsplit(v.x,h0,l0); bsplit(v.y,h1,l1); bsplit(v.z,h2,l2); bsplit(v.w,h3,l3);
    *(uint2*)(dh + e) = make_uint2(pack2(h0,h1), pack2(h2,h3));
    *(uint2*)(dl + e) = make_uint2(pack2(l0,l1), pack2(l2,l3));
}

// ---------------- MMA helpers ----------------
__device__ __forceinline__ void ldsm4(unsigned r[4], const void* p) {
    unsigned a = (unsigned)__cvta_generic_to_shared(p);
    asm volatile("ldmatrix.sync.aligned.m8n8.x4.shared.b16 {%0,%1,%2,%3}, [%4];"
        : "=r"(r[0]), "=r"(r[1]), "=r"(r[2]), "=r"(r[3]) : "r"(a));
}
__device__ __forceinline__ void ldsm4t(unsigned r[4], const void* p) {
    unsigned a = (unsigned)__cvta_generic_to_shared(p);
    asm volatile("ldmatrix.sync.aligned.m8n8.x4.trans.shared.b16 {%0,%1,%2,%3}, [%4];"
        : "=r"(r[0]), "=r"(r[1]), "=r"(r[2]), "=r"(r[3]) : "r"(a));
}
__device__ __forceinline__ void mma16816(float c[4], const unsigned a[4],
                                         unsigned b0, unsigned b1) {
    asm volatile("mma.sync.aligned.m16n8k16.row.col.f32.bf16.bf16.f32 "
        "{%0,%1,%2,%3}, {%4,%5,%6,%7}, {%8,%9}, {%0,%1,%2,%3};"
        : "+f"(c[0]), "+f"(c[1]), "+f"(c[2]), "+f"(c[3])
        : "r"(a[0]), "r"(a[1]), "r"(a[2]), "r"(a[3]), "r"(b0), "r"(b1));
}
__device__ __forceinline__ void cpasync16(unsigned dst, const void* src) {
    asm volatile("cp.async.ca.shared.global [%0], [%1], 16;" :: "r"(dst), "l"(src));
}
// direct-global A fragment (m16n8k16 row-major lane map; validated round-8)
__device__ __forceinline__ void ldafrag(unsigned f[4], const bf16* base, int K) {
    f[0] = *(const unsigned*)(base);
    f[1] = *(const unsigned*)(base + 8 * (size_t)K);
    f[2] = *(const unsigned*)(base + 8);
    f[3] = *(const unsigned*)(base + 8 * (size_t)K + 8);
}

// ====== shared GEMM geometry (v5 template) ============
#define ASTR 24
#define BSTR5 72
#define ST_A 3072
#define ST_B5 1152
#define ST_TOT5 8448

// ====== QKV GEMM v6: A direct-global fragments, B cp.async only ===========
// B-stage per (stage, part): 16x72 bf16 = 1152 elems. 2 stages x 2 parts.
#define ST_B6 1152
#define ST_STAGE6 2304    // 2 parts

// blocks [0,96): y (K=512, first: 2b x 3m x 16n); [96,480): x (2b x 3m x 64n)
__global__ void __launch_bounds__(256) qkv_mma6_kernel(
    const float* __restrict__ bx, const float* __restrict__ by_)
{
    __shared__ __align__(16) char SMB[16896];   // B stages 9216B | Cst 16KB
    bf16* SM = (bf16*)SMB;
    float* Cst = (float*)SMB;

    const bf16 *Wh, *Wl, *Xh, *Xl;
    const float* bias;
    bf16 *Qh_, *Ql_, *Kh_, *Kl_, *Vh_, *Vl_;
    int N, K, m0, n0, b;
    int blk = blockIdx.x;
    if (blk < 96) {
        N = HWY; K = Y_CH;
        b = blk / 48; int r = blk % 48; m0 = (r % 3) * 128; n0 = (r / 3) * 64;
        Wh = g_wyqh; Wl = g_wyql;
        Xh = g_ysh + (size_t)b * K * N; Xl = g_ysl + (size_t)b * K * N;
        bias = by_;
        Qh_=g_qyh; Ql_=g_qyl; Kh_=g_kyh; Kl_=g_kyl; Vh_=g_vyh; Vl_=g_vyl;
    } else {
        blk -= 96;
        N = HWX; K = X_CH;
        b = blk / 192; int r = blk % 192; m0 = (r % 3) * 128; n0 = (r / 3) * 64;
        Wh = g_wxqh; Wl = g_wxql;
        Xh = g_xsh + (size_t)b * K * N; Xl = g_xsl + (size_t)b * K * N;
        bias = bx;
        Qh_=g_qxh; Ql_=g_qxl; Kh_=g_kxh; Kl_=g_kxl; Vh_=g_vxh; Vl_=g_vxl;
    }

    const int tid = threadIdx.x, lane = tid & 31;
    const int w = tid >> 5;
    const int wm = w & 3, wn = w >> 2;            // 4 m-warps x 2 n-warps
    const int bkrow = (lane & 7) + ((lane & 8) ? 8 : 0);
    const int bncol = (lane & 16) ? 8 : 0;
    const int rA = lane >> 2, cA = (lane & 3) * 2; // A fragment lane map

    const unsigned sbase = (unsigned)__cvta_generic_to_shared(SMB);

    // B stage-fill: exactly 1 cp.async per thread
    const int fpart = tid >> 7;                    // 0..1
    const int frid  = tid & 127;                   // 0..127
    const int fkrow = frid >> 3, fnc = frid & 7;
    auto fill = [&](int s, int kc) {
        unsigned bdst = sbase + (unsigned)(s*ST_STAGE6 + fpart*ST_B6 + fkrow*BSTR5 + fnc*8) * 2;
        cpasync16(bdst, (fpart ? Xl : Xh) + (size_t)(kc*16 + fkrow) * N + n0 + fnc*8);
        asm volatile("cp.async.commit_group;");
    };

    float acc[2][4][4] = {};
    const int nkc = K >> 4;

    fill(0, 0);
    for (int kc = 0; kc < nkc; kc++) {
        const int s = kc & 1;

        // A fragments direct from global (L1/L2-resident W) — issued before
        // the wait so LDG latency overlaps the pipeline wait + ldsm.
        unsigned ah[2][4], al[2][4];
        #pragma unroll
        for (int im = 0; im < 2; im++) {
            size_t ao = (size_t)(m0 + wm*32 + im*16 + rA) * K + kc*16 + cA;
            ldafrag(ah[im], Wh + ao, K);
            ldafrag(al[im], Wl + ao, K);
        }

        if (kc + 1 < nkc) {
            fill(s ^ 1, kc + 1);
            asm volatile("cp.async.wait_group 1;" ::: "memory");
        } else {
            asm volatile("cp.async.wait_group 0;" ::: "memory");
        }
        __syncthreads();

        const bf16* Bh = SM + s*ST_STAGE6;
        const bf16* Bl = Bh + ST_B6;

        #pragma unroll
        for (int jn = 0; jn < 2; jn++) {
            unsigned bh4[4], bl4[4];
            const int boff = bkrow * BSTR5 + wn*32 + jn*16 + bncol;
            ldsm4t(bh4, &Bh[boff]);
            ldsm4t(bl4, &Bl[boff]);
            #pragma unroll
            for (int im = 0; im < 2; im++) {
                mma16816(acc[im][2*jn],   ah[im], bh4[0], bh4[1]);
                mma16816(acc[im][2*jn],   al[im], bh4[0], bh4[1]);
                mma16816(acc[im][2*jn],   ah[im], bl4[0], bl4[1]);
                mma16816(acc[im][2*jn+1], ah[im], bh4[2], bh4[3]);
                mma16816(acc[im][2*jn+1], al[im], bh4[2], bh4[3]);
                mma16816(acc[im][2*jn+1], ah[im], bl4[2], bl4[3]);
            }
        }
        __syncthreads();
    }

    // staged epilogue (validated): fragments -> smem fp32 (64x64) -> scatter
    const int r = lane >> 2, cq = (lane & 3) * 2;
    #pragma unroll
    for (int im = 0; im < 2; im++) {
        __syncthreads();
        #pragma unroll
        for (int j8 = 0; j8 < 4; j8++) {
            int col = wn*32 + j8*8 + cq;
            Cst[(wm*16 + r) * 64 + col]         = acc[im][j8][0];
            Cst[(wm*16 + r) * 64 + col + 1]     = acc[im][j8][1];
            Cst[(wm*16 + r + 8) * 64 + col]     = acc[im][j8][2];
            Cst[(wm*16 + r + 8) * 64 + col + 1] = acc[im][j8][3];
        }
        __syncthreads();
        for (int idx = tid; idx < 64*64; idx += 256) {
            int srow = idx >> 6, scol = idx & 63;
            int o = m0 + (srow >> 4) * 32 + im*16 + (srow & 15);
            int n = n0 + scol;
            float v = Cst[idx] + bias[o];
            int t = o >> 7, h = (o & 127) >> 5, d = o & 31;
            bf16 hh, ll;
            if (t == 0) {
                bsplit(v * GAMMA_L2E, hh, ll);
                size_t i2 = ((size_t)(b*NHEAD + h) * N + n) * HD + d;
                Qh_[i2] = hh;  Ql_[i2] = ll;
            } else if (t == 1) {
                bsplit(v, hh, ll);
                size_t i2 = ((size_t)(b*NHEAD + h) * N + n) * HD + d;
                Kh_[i2] = hh;  Kl_[i2] = ll;
            } else {
                bsplit(v, hh, ll);
                size_t i2 = ((size_t)(b*NHEAD + h) * HD + d) * N + n;
                Vh_[i2] = hh;  Vl_[i2] = ll;
            }
        }
    }
}

// ====== proj tensor-core GEMM (validated round-14) =========================
__global__ void __launch_bounds__(256) proj_mma_kernel(
    const float* __restrict__ bpx, const float* __restrict__ Rx,
    const float* __restrict__ bpy, const float* __restrict__ Ry,
    float* __restrict__ outp)
{
    __shared__ __align__(16) char SMB[33792];
    bf16* SM = (bf16*)SMB;
    float* Cst = (float*)SMB;

    const bf16 *Wh, *Wl, *Xh, *Xl;
    const float *bias, *Res;
    float* Out;
    int N, OC, m0, n0, b;
    int blk = blockIdx.x;
    if (blk < 128) {
        N = HWY; OC = Y_CH;
        b = blk / 64; int r = blk % 64; m0 = (r % 4) * 128; n0 = (r / 4) * 64;
        Wh = g_wpyh; Wl = g_wpyl;
        Xh = g_ayh + (size_t)b * DIM * N; Xl = g_ayl + (size_t)b * DIM * N;
        bias = bpy; Res = Ry; Out = outp + (size_t)BATCH * X_CH * HWX;
    } else {
        blk -= 128;
        N = HWX; OC = X_CH;
        b = blk / 128; int r = blk % 128; m0 = (r % 2) * 128; n0 = (r / 2) * 64;
        Wh = g_wpxh; Wl = g_wpxl;
        Xh = g_axh + (size_t)b * DIM * N; Xl = g_axl + (size_t)b * DIM * N;
        bias = bpx; Res = Rx; Out = outp;
    }
    const int K = DIM;

    const int tid = threadIdx.x, lane = tid & 31;
    const int w = tid >> 5;
    const int wm = w & 3, wn = w >> 2;
    const int arow = (lane & 7) + ((lane & 8) ? 8 : 0);
    const int acol = (lane & 16) ? 8 : 0;
    const int bkrow = (lane & 7) + ((lane & 8) ? 8 : 0);
    const int bncol = (lane & 16) ? 8 : 0;

    const unsigned sbase = (unsigned)__cvta_generic_to_shared(SMB);

    auto fill = [&](int s, int kc) {
        #pragma unroll
        for (int it = 0; it < 3; it++) {
            int id = tid + it * 256;
            if (id < 512) {
                int part = id & 1, rid = id >> 1;
                int row = rid >> 1, cc = rid & 1;
                unsigned adst = sbase + (unsigned)(s*ST_TOT5 + part*ST_A + row*ASTR + cc*8) * 2;
                cpasync16(adst, (part ? Wl : Wh) + (size_t)(m0 + row) * K + kc*16 + cc*8);
            } else {
                int j = id - 512;
                int part = j & 1, rid2 = j >> 1;
                int krow = rid2 >> 3, nc = rid2 & 7;
                unsigned bdst = sbase + (unsigned)(s*ST_TOT5 + 2*ST_A + part*ST_B5 + krow*BSTR5 + nc*8) * 2;
                cpasync16(bdst, (part ? Xl : Xh) + (size_t)(kc*16 + krow) * N + n0 + nc*8);
            }
        }
        asm volatile("cp.async.commit_group;");
    };

    float acc[2][4][4] = {};
    const int nkc = K >> 4;

    fill(0, 0);
    for (int kc = 0; kc < nkc; kc++) {
        const int s = kc & 1;
        if (kc + 1 < nkc) {
            fill(s ^ 1, kc + 1);
            asm volatile("cp.async.wait_group 1;" ::: "memory");
        } else {
            asm volatile("cp.async.wait_group 0;" ::: "memory");
        }
        __syncthreads();

        const bf16* Ah = SM + s*ST_TOT5;
        const bf16* Al = Ah + ST_A;
        const bf16* Bh = SM + s*ST_TOT5 + 2*ST_A;
        const bf16* Bl = Bh + ST_B5;

        unsigned ah[2][4], al[2][4];
        #pragma unroll
        for (int im = 0; im < 2; im++) {
            ldsm4(ah[im], &Ah[(wm*32 + im*16 + arow) * ASTR + acol]);
            ldsm4(al[im], &Al[(wm*32 + im*16 + arow) * ASTR + acol]);
        }
        #pragma unroll
        for (int jn = 0; jn < 2; jn++) {
            unsigned bh4[4], bl4[4];
            const int boff = bkrow * BSTR5 + wn*32 + jn*16 + bncol;
            ldsm4t(bh4, &Bh[boff]);
            ldsm4t(bl4, &Bl[boff]);
            #pragma unroll
            for (int im = 0; im < 2; im++) {
                mma16816(acc[im][2*jn],   ah[im], bh4[0], bh4[1]);
                mma16816(acc[im][2*jn],   al[im], bh4[0], bh4[1]);
                mma16816(acc[im][2*jn],   ah[im], bl4[0], bl4[1]);
                mma16816(acc[im][2*jn+1], ah[im], bh4[2], bh4[3]);
                mma16816(acc[im][2*jn+1], al[im], bh4[2], bh4[3]);
                mma16816(acc[im][2*jn+1], ah[im], bl4[2], bl4[3]);
            }
        }
        __syncthreads();
    }

    const int r = lane >> 2, cq = (lane & 3) * 2;
    #pragma unroll
    for (int im = 0; im < 2; im++) {
        __syncthreads();
        #pragma unroll
        for (int j8 = 0; j8 < 4; j8++) {
            int col = wn*32 + j8*8 + cq;
            Cst[(wm*16 + r) * 64 + col]         = acc[im][j8][0];
            Cst[(wm*16 + r) * 64 + col + 1]     = acc[im][j8][1];
            Cst[(wm*16 + r + 8) * 64 + col]     = acc[im][j8][2];
            Cst[(wm*16 + r + 8) * 64 + col + 1] = acc[im][j8][3];
        }
        __syncthreads();
        for (int idx = tid; idx < 64*64; idx += 256) {
            int srow = idx >> 6, scol = idx & 63;
            int o = m0 + (srow >> 4) * 32 + im*16 + (srow & 15);
            int n = n0 + scol;
            size_t off = ((size_t)b * OC + o) * N + n;
            Out[off] = Cst[idx] + bias[o] + Res[off];
        }
    }
}

// ====== MMA flash attention (validated round-14) ===========================
#define QSTR 40
#define VSTR 72
#define OFF_KH 0
#define OFF_KL 2560
#define OFF_VH 5120
#define OFF_VL 7424
#define STAGE_ELEMS 9728

__global__ void __launch_bounds__(128) attn_mma_kernel()
{
    __shared__ __align__(16) bf16 KV[2][STAGE_ELEMS];

    int blk = blockIdx.x;
    const bf16 *Qh, *Ql, *Kh, *Kl, *Vh, *Vl;
    bf16 *Oh_ = nullptr, *Ol_ = nullptr;
    int NQ, NK, bh, q0, kt0, sp = 0;
    bool split;
    if (blk < 512) {
        split = true;
        bh = blk >> 6;
        int r2 = blk & 63;
        q0 = (r2 >> 2) * 64;
        sp = r2 & 3;
        kt0 = sp * 16;
        NQ = HWY; NK = HWX;
        Qh=g_qyh; Ql=g_qyl; Kh=g_kxh; Kl=g_kxl; Vh=g_vxh; Vl=g_vxl;
    } else {
        split = false;
        blk -= 512;
        bh = blk >> 6; q0 = (blk & 63) * 64; kt0 = 0; NQ = HWX; NK = HWY;
        Qh=g_qxh; Ql=g_qxl; Kh=g_kyh; Kl=g_kyl; Vh=g_vyh; Vl=g_vyl;
        Oh_ = g_axh; Ol_ = g_axl;
    }
    const int nt = 16;

    const int tid = threadIdx.x, w = tid >> 5, lane = tid & 31;
    const size_t kbase = (size_t)bh * NK * HD;
    const size_t vbase = (size_t)bh * HD * NK;

    const int e0 = tid * 8, e1 = (tid + 128) * 8;
    const int ks0 = (e0 >> 5) * QSTR + (e0 & 31);
    const int ks1 = (e1 >> 5) * QSTR + (e1 & 31);
    const int vs0 = (e0 >> 6) * VSTR + (e0 & 63);
    const int vs1 = (e1 >> 6) * VSTR + (e1 & 63);
    const size_t kg0 = (size_t)(e0 >> 5) * HD + (e0 & 31);
    const size_t kg1 = (size_t)(e1 >> 5) * HD + (e1 & 31);
    const size_t vg0 = (size_t)(e0 >> 6) * NK + (e0 & 63);
    const size_t vg1 = (size_t)(e1 >> 6) * NK + (e1 & 63);

    unsigned sb0 = (unsigned)__cvta_generic_to_shared(&KV[0][0]);
    unsigned sb1 = (unsigned)__cvta_generic_to_shared(&KV[1][0]);

    {
        size_t ka = kbase + (size_t)kt0 * 64 * HD;
        size_t va = vbase + (size_t)kt0 * 64;
        cpasync16(sb0 + (OFF_KH + ks0) * 2, Kh + ka + kg0);
        cpasync16(sb0 + (OFF_KH + ks1) * 2, Kh + ka + kg1);
        cpasync16(sb0 + (OFF_KL + ks0) * 2, Kl + ka + kg0);
        cpasync16(sb0 + (OFF_KL + ks1) * 2, Kl + ka + kg1);
        cpasync16(sb0 + (OFF_VH + vs0) * 2, Vh + va + vg0);
        cpasync16(sb0 + (OFF_VH + vs1) * 2, Vh + va + vg1);
        cpasync16(sb0 + (OFF_VL + vs0) * 2, Vl + va + vg0);
        cpasync16(sb0 + (OFF_VL + vs1) * 2, Vl + va + vg1);
        asm volatile("cp.async.commit_group;");
    }

    {
        bf16* Qsh = &KV[1][0];
        bf16* Qsl = &KV[1][2560];
        const size_t qb = (size_t)bh * NQ * HD + (size_t)q0 * HD;
        #pragma unroll
        for (int it = 0; it < 2; it++) {
            int e = (tid + it * 128) * 8;
            int row = e >> 5, col = e & 31;
            *(uint4*)&Qsh[row * QSTR + col] = *(const uint4*)(Qh + qb + (size_t)row * HD + col);
            *(uint4*)&Qsl[row * QSTR + col] = *(const uint4*)(Ql + qb + (size_t)row * HD + col);
        }
    }
    __syncthreads();

    const int arow = (lane & 7) + ((lane & 8) ? 8 : 0);
    const int acol = (lane & 16) ? 8 : 0;
    const int brow = (lane & 7) + ((lane & 16) ? 8 : 0);
    const int bcol = (lane & 8) ? 8 : 0;
    unsigned qf[2][2][4];
    #pragma unroll
    for (int p = 0; p < 2; p++)
        #pragma unroll
        for (int c = 0; c < 2; c++)
            ldsm4(qf[p][c], &KV[1][p * 2560 + (w * 16 + arow) * QSTR + c * 16 + acol]);
    __syncthreads();

    float m0r = -1e30f, m1r = -1e30f, l0 = 0.f, l1 = 0.f;
    float oacc[4][4] = {};

    for (int i = 0; i < nt; i++) {
        const int s = i & 1;
        if (i + 1 < nt) {
            unsigned sb = (s ^ 1) ? sb1 : sb0;
            size_t ka = kbase + (size_t)(kt0 + i + 1) * 64 * HD;
            size_t va = vbase + (size_t)(kt0 + i + 1) * 64;
            cpasync16(sb + (OFF_KH + ks0) * 2, Kh + ka + kg0);
            cpasync16(sb + (OFF_KH + ks1) * 2, Kh + ka + kg1);
            cpasync16(sb + (OFF_KL + ks0) * 2, Kl + ka + kg0);
            cpasync16(sb + (OFF_KL + ks1) * 2, Kl + ka + kg1);
            cpasync16(sb + (OFF_VH + vs0) * 2, Vh + va + vg0);
            cpasync16(sb + (OFF_VH + vs1) * 2, Vh + va + vg1);
            cpasync16(sb + (OFF_VL + vs0) * 2, Vl + va + vg0);
            cpasync16(sb + (OFF_VL + vs1) * 2, Vl + va + vg1);
            asm volatile("cp.async.commit_group;");
            asm volatile("cp.async.wait_group 1;" ::: "memory");
        } else {
            asm volatile("cp.async.wait_group 0;" ::: "memory");
        }
        __syncthreads();

        const bf16* Ks0 = &KV[s][OFF_KH];
        const bf16* Ks1 = &KV[s][OFF_KL];
        const bf16* Vs0 = &KV[s][OFF_VH];
        const bf16* Vs1 = &KV[s][OFF_VL];

        float sreg[8][4];
        #pragma unroll
        for (int nb = 0; nb < 8; nb++)
            sreg[nb][0] = sreg[nb][1] = sreg[nb][2] = sreg[nb][3] = 0.f;

        #pragma unroll
        for (int c = 0; c < 2; c++) {
            #pragma unroll
            for (int jp = 0; jp < 4; jp++) {
                unsigned kh4[4], kl4[4];
                ldsm4(kh4, &Ks0[(jp * 16 + brow) * QSTR + c * 16 + bcol]);
                ldsm4(kl4, &Ks1[(jp * 16 + brow) * QSTR + c * 16 + bcol]);
                mma16816(sreg[2*jp],   qf[0][c], kh4[0], kh4[1]);
                mma16816(sreg[2*jp],   qf[1][c], kh4[0], kh4[1]);
                mma16816(sreg[2*jp],   qf[0][c], kl4[0], kl4[1]);
                mma16816(sreg[2*jp+1], qf[0][c], kh4[2], kh4[3]);
                mma16816(sreg[2*jp+1], qf[1][c], kh4[2], kh4[3]);
                mma16816(sreg[2*jp+1], qf[0][c], kl4[2], kl4[3]);
            }
        }

        float mx0 = sreg[0][0], mx1 = sreg[0][2];
        #pragma unroll
        for (int nb = 0; nb < 8; nb++) {
            mx0 = fmaxf(mx0, fmaxf(sreg[nb][0], sreg[nb][1]));
            mx1 = fmaxf(mx1, fmaxf(sreg[nb][2], sreg[nb][3]));
        }
        mx0 = fmaxf(mx0, __shfl_xor_sync(~0u, mx0, 1));
        mx0 = fmaxf(mx0, __shfl_xor_sync(~0u, mx0, 2));
        mx1 = fmaxf(mx1, __shfl_xor_sync(~0u, mx1, 1));
        mx1 = fmaxf(mx1, __shfl_xor_sync(~0u, mx1, 2));
        float nm0 = fmaxf(m0r, mx0), nm1 = fmaxf(m1r, mx1);
        float sc0 = exp2f(m0r - nm0), sc1 = exp2f(m1r - nm1);
        m0r = nm0; m1r = nm1;
        float rs0 = 0.f, rs1 = 0.f;
        #pragma unroll
        for (int nb = 0; nb < 8; nb++) {
            sreg[nb][0] = exp2f(sreg[nb][0] - nm0);
            sreg[nb][1] = exp2f(sreg[nb][1] - nm0);
            sreg[nb][2] = exp2f(sreg[nb][2] - nm1);
            sreg[nb][3] = exp2f(sreg[nb][3] - nm1);
            rs0 += sreg[nb][0] + sreg[nb][1];
            rs1 += sreg[nb][2] + sreg[nb][3];
        }
        rs0 += __shfl_xor_sync(~0u, rs0, 1);
        rs0 += __shfl_xor_sync(~0u, rs0, 2);
        rs1 += __shfl_xor_sync(~0u, rs1, 1);
        rs1 += __shfl_xor_sync(~0u, rs1, 2);
        l0 = l0 * sc0 + rs0;  l1 = l1 * sc1 + rs1;
        #pragma unroll
        for (int nb = 0; nb < 4; nb++) {
            oacc[nb][0] *= sc0; oacc[nb][1] *= sc0;
            oacc[nb][2] *= sc1; oacc[nb][3] *= sc1;
        }

        #pragma unroll
        for (int c = 0; c < 4; c++) {
            unsigned pah[4], pal[4];
            #pragma unroll
            for (int r4 = 0; r4 < 4; r4++) {
                int nb = 2 * c + (r4 >> 1);
                int pr = (r4 & 1) * 2;
                psplit2(sreg[nb][pr], sreg[nb][pr + 1], pah[r4], pal[r4]);
            }
            #pragma unroll
            for (int np = 0; np < 2; np++) {
                unsigned vh4[4], vl4[4];
                ldsm4(vh4, &Vs0[(np * 16 + brow) * VSTR + c * 16 + bcol]);
                ldsm4(vl4, &Vs1[(np * 16 + brow) * VSTR + c * 16 + bcol]);
                mma16816(oacc[2*np],   pah, vh4[0], vh4[1]);
                mma16816(oacc[2*np],   pal, vh4[0], vh4[1]);
                mma16816(oacc[2*np],   pah, vl4[0], vl4[1]);
                mma16816(oacc[2*np+1], pah, vh4[2], vh4[3]);
                mma16816(oacc[2*np+1], pal, vh4[2], vh4[3]);
                mma16816(oacc[2*np+1], pah, vl4[2], vl4[3]);
            }
        }
        __syncthreads();
    }

    int r = lane >> 2;
    int qg = q0 + w * 16 + r;
    if (split) {
        size_t pb = ((size_t)sp * 8 + bh) * HWY;
        #pragma unroll
        for (int nb = 0; nb < 4; nb++) {
            int d = nb * 8 + (lane & 3) * 2;
            *(float2*)&g_pacc[(pb + qg) * HD + d]     = make_float2(oacc[nb][0], oacc[nb][1]);
            *(float2*)&g_pacc[(pb + qg + 8) * HD + d] = make_float2(oacc[nb][2], oacc[nb][3]);
        }
        if ((lane & 3) == 0) {
            g_pml[pb + qg]     = make_float2(m0r, l0);
            g_pml[pb + qg + 8] = make_float2(m1r, l1);
        }
    } else {
        float inv0 = 1.f / l0, inv1 = 1.f / l1;
        size_t ob = (size_t)bh * HD * NQ;
        #pragma unroll
        for (int nb = 0; nb < 4; nb++) {
            int d = nb * 8 + (lane & 3) * 2;
            bf16 hh, ll;
            bsplit(oacc[nb][0] * inv0, hh, ll);
            Oh_[ob + (size_t)d * NQ + qg] = hh;       Ol_[ob + (size_t)d * NQ + qg] = ll;
            bsplit(oacc[nb][1] * inv0, hh, ll);
            Oh_[ob + (size_t)(d+1) * NQ + qg] = hh;   Ol_[ob + (size_t)(d+1) * NQ + qg] = ll;
            bsplit(oacc[nb][2] * inv1, hh, ll);
            Oh_[ob + (size_t)d * NQ + qg + 8] = hh;   Ol_[ob + (size_t)d * NQ + qg + 8] = ll;
            bsplit(oacc[nb][3] * inv1, hh, ll);
            Oh_[ob + (size_t)(d+1) * NQ + qg + 8] = hh; Ol_[ob + (size_t)(d+1) * NQ + qg + 8] = ll;
        }
    }
}

// ====== combine split-K partials (validated round-14) ======================
__global__ void __launch_bounds__(128) attn_combine_kernel()
{
    int t = blockIdx.x * 128 + threadIdx.x;
    int bh = t >> 10, q = t & 1023;
    float2 ml[4];
    float M = -1e30f;
    #pragma unroll
    for (int s = 0; s < 4; s++) {
        ml[s] = g_pml[((size_t)s * 8 + bh) * HWY + q];
        M = fmaxf(M, ml[s].x);
    }
    float wgt[4], L = 0.f;
    #pragma unroll
    for (int s = 0; s < 4; s++) {
        wgt[s] = exp2f(ml[s].x - M);
        L += wgt[s] * ml[s].y;
    }
    float invL = 1.f / L;
    size_t ob = (size_t)bh * HD * HWY;
    #pragma unroll
    for (int d4 = 0; d4 < HD; d4 += 4) {
        float4 o = make_float4(0.f, 0.f, 0.f, 0.f);
        #pragma unroll
        for (int s = 0; s < 4; s++) {
            const float* a = g_pacc + (((size_t)s * 8 + bh) * HWY + q) * HD;
            float4 v = *(const float4*)(a + d4);
            o.x += wgt[s] * v.x;  o.y += wgt[s] * v.y;
            o.z += wgt[s] * v.z;  o.w += wgt[s] * v.w;
        }
        float vals[4] = {o.x * invL, o.y * invL, o.z * invL, o.w * invL};
        #pragma unroll
        for (int j = 0; j < 4; j++) {
            bf16 hh, ll; bsplit(vals[j], hh, ll);
            g_ayh[ob + (size_t)(d4 + j) * HWY + q] = hh;
            g_ayl[ob + (size_t)(d4 + j) * HWY + q] = ll;
        }
    }
}

// ============================== launcher ==================================
extern "C" void kernel_launch(void* const* d_in, const int* in_sizes, int n_in,
                              void* d_out, int out_size)
{
    (void)out_size;
    const float *x=0, *y=0, *wxq=0, *bxq=0, *wyq=0, *byq=0,
                *wpx=0, *bpx=0, *wpy=0, *bpy=0;
    for (int i = 0; i < n_in; i++) {
        const float* p = (const float*)d_in[i];
        switch (in_sizes[i]) {
            case 2097152: x = p;   break;
            case 1048576: y = p;   break;
            case 98304:   wxq = p; break;
            case 196608:  wyq = p; break;
            case 32768:   wpx = p; break;
            case 65536:   wpy = p; break;
            case 256:     bpx = p; break;
            case 512:     bpy = p; break;
            case 384:     if (!bxq) bxq = p; else byq = p; break;
            default: break;
        }
    }
    float* out = (float*)d_out;

    split_w_kernel<<<384, 256>>>(wxq, wyq, wpx, wpy);
    presplit_x_kernel<<<3072, 256>>>(x, y);
    qkv_mma6_kernel<<<480, 256>>>(bxq, byq);
    attn_mma_kernel<<<1024, 128>>>();
    attn_combine_kernel<<<64, 128>>>();
    proj_mma_kernel<<<384, 256>>>(bpx, x, bpy, y, out);
}

// round 16
// speedup vs baseline: 1.0647x; 1.0647x over previous
#include <cuda_runtime.h>
#include <cuda_bf16.h>

#define X_CH   256
#define Y_CH   512
#define DIM    128
#define NHEAD  4
#define HD     32
#define HWX    4096
#define HWY    1024
#define BATCH  2
#define GAMMA  0.17677669529663687f
#define GAMMA_L2E (0.17677669529663687f * 1.4426950408889634f)

typedef __nv_bfloat16 bf16;

// ---------------- scratch (device globals; no allocation) ----------------
static __device__ __align__(16) bf16 g_qxh[BATCH*NHEAD*HWX*HD], g_qxl[BATCH*NHEAD*HWX*HD];
static __device__ __align__(16) bf16 g_kxh[BATCH*NHEAD*HWX*HD], g_kxl[BATCH*NHEAD*HWX*HD];
static __device__ __align__(16) bf16 g_vxh[BATCH*NHEAD*HWX*HD], g_vxl[BATCH*NHEAD*HWX*HD];
static __device__ __align__(16) bf16 g_qyh[BATCH*NHEAD*HWY*HD], g_qyl[BATCH*NHEAD*HWY*HD];
static __device__ __align__(16) bf16 g_kyh[BATCH*NHEAD*HWY*HD], g_kyl[BATCH*NHEAD*HWY*HD];
static __device__ __align__(16) bf16 g_vyh[BATCH*NHEAD*HWY*HD], g_vyl[BATCH*NHEAD*HWY*HD];
// attention out, split bf16, TRANSPOSED [b, c=h*32+d, q]
static __device__ __align__(16) bf16 g_axh[BATCH*DIM*HWX], g_axl[BATCH*DIM*HWX];
static __device__ __align__(16) bf16 g_ayh[BATCH*DIM*HWY], g_ayl[BATCH*DIM*HWY];
// pre-split weights [M][K] and inputs [B][C][N]
static __device__ __align__(16) bf16 g_wxqh[384*X_CH], g_wxql[384*X_CH];
static __device__ __align__(16) bf16 g_wyqh[384*Y_CH], g_wyql[384*Y_CH];
static __device__ __align__(16) bf16 g_wpxh[X_CH*DIM], g_wpxl[X_CH*DIM];
static __device__ __align__(16) bf16 g_wpyh[Y_CH*DIM], g_wpyl[Y_CH*DIM];
static __device__ __align__(16) bf16 g_xsh[BATCH*X_CH*HWX], g_xsl[BATCH*X_CH*HWX];
static __device__ __align__(16) bf16 g_ysh[BATCH*Y_CH*HWY], g_ysl[BATCH*Y_CH*HWY];
// split-K partials for dir1
static __device__ __align__(16) float  g_pacc[4*BATCH*NHEAD*HWY*HD];
static __device__ __align__(16) float2 g_pml[4*BATCH*NHEAD*HWY];

__device__ __forceinline__ void bsplit(float v, bf16& h, bf16& l) {
    h = __float2bfloat16(v);
    l = __float2bfloat16(v - __bfloat162float(h));
}
__device__ __forceinline__ unsigned pack2(bf16 a, bf16 b) {
    return (unsigned)__bfloat16_as_ushort(a) | ((unsigned)__bfloat16_as_ushort(b) << 16);
}
__device__ __forceinline__ void psplit2(float x0, float x1, unsigned& ph, unsigned& pl) {
    unsigned h;
    asm("cvt.rn.bf16x2.f32 %0, %1, %2;" : "=r"(h) : "f"(x1), "f"(x0));
    float h0 = __uint_as_float(h << 16);
    float h1 = __uint_as_float(h & 0xffff0000u);
    float e0 = x0 - h0, e1 = x1 - h1;
    asm("cvt.rn.bf16x2.f32 %0, %1, %2;" : "=r"(pl) : "f"(e1), "f"(e0));
    ph = h;
}

// ---------------- prep: split all 4 weight matrices (validated) -----------
__global__ void __launch_bounds__(256) split_w_kernel(
    const float* __restrict__ s0, const float* __restrict__ s1,
    const float* __restrict__ s2, const float* __restrict__ s3)
{
    int e = (blockIdx.x * 256 + threadIdx.x) * 4;
    const float* s; bf16 *dh, *dl;
    if (e < 98304)       { s = s0; dh = g_wxqh; dl = g_wxql; }
    else if (e < 294912) { e -= 98304;  s = s1; dh = g_wyqh; dl = g_wyql; }
    else if (e < 327680) { e -= 294912; s = s2; dh = g_wpxh; dl = g_wpxl; }
    else                 { e -= 327680; s = s3; dh = g_wpyh; dl = g_wpyl; }
    float4 v = *(const float4*)(s + e);
    bf16 h0,l0,h1,l1,h2,l2,h3,l3;
    bsplit(v.x,h0,l0); bsplit(v.y,h1,l1); bsplit(v.z,h2,l2); bsplit(v.w,h3,l3);
    *(uint2*)(dh + e) = make_uint2(pack2(h0,h1), pack2(h2,h3));
    *(uint2*)(dl + e) = make_uint2(pack2(l0,l1), pack2(l2,l3));
}

// ---------------- prep: split inputs elementwise (validated) ----------
__global__ void __launch_bounds__(256) presplit_x_kernel(
    const float* __restrict__ x, const float* __restrict__ y)
{
    int e = (blockIdx.x * 256 + threadIdx.x) * 4;
    const float* s; bf16 *dh, *dl;
    if (e < BATCH*X_CH*HWX) { s = x; dh = g_xsh; dl = g_xsl; }
    else { e -= BATCH*X_CH*HWX; s = y; dh = g_ysh; dl = g_ysl; }
    float4 v = *(const float4*)(s + e);
    bf16 h0,l0,h1,l1,h2,l2,h3,l3;
    bsplit(v.x,h0,l0); bsplit(v.y,h1,l1); bsplit(v.z,h2,l2); bsplit(v.w,h3,l3);
    *(uint2*)(dh + e) = make_uint2(pack2(h0,h1), pack2(h2,h3));
    *(uint2*)(dl + e) = make_uint2(pack2(l0,l1), pack2(l2,l3));
}

// ---------------- MMA helpers ----------------
__device__ __forceinline__ void ldsm4(unsigned r[4], const void* p) {
    unsigned a = (unsigned)__cvta_generic_to_shared(p);
    asm volatile("ldmatrix.sync.aligned.m8n8.x4.shared.b16 {%0,%1,%2,%3}, [%4];"
        : "=r"(r[0]), "=r"(r[1]), "=r"(r[2]), "=r"(r[3]) : "r"(a));
}
__device__ __forceinline__ void ldsm4t(unsigned r[4], const void* p) {
    unsigned a = (unsigned)__cvta_generic_to_shared(p);
    asm volatile("ldmatrix.sync.aligned.m8n8.x4.trans.shared.b16 {%0,%1,%2,%3}, [%4];"
        : "=r"(r[0]), "=r"(r[1]), "=r"(r[2]), "=r"(r[3]) : "r"(a));
}
__device__ __forceinline__ void mma16816(float c[4], const unsigned a[4],
                                         unsigned b0, unsigned b1) {
    asm volatile("mma.sync.aligned.m16n8k16.row.col.f32.bf16.bf16.f32 "
        "{%0,%1,%2,%3}, {%4,%5,%6,%7}, {%8,%9}, {%0,%1,%2,%3};"
        : "+f"(c[0]), "+f"(c[1]), "+f"(c[2]), "+f"(c[3])
        : "r"(a[0]), "r"(a[1]), "r"(a[2]), "r"(a[3]), "r"(b0), "r"(b1));
}
__device__ __forceinline__ void cpasync16(unsigned dst, const void* src) {
    asm volatile("cp.async.ca.shared.global [%0], [%1], 16;" :: "r"(dst), "l"(src));
}

// ====== shared GEMM geometry (v5 template, validated) ============
#define ASTR 24
#define BSTR5 72
#define ST_A 3072
#define ST_B5 1152
#define ST_TOT5 8448

// ====== QKV tensor-core GEMM v5 (validated round-13/14) ===================
__global__ void __launch_bounds__(256) qkv_mma5_kernel(
    const float* __restrict__ bx, const float* __restrict__ by_)
{
    __shared__ __align__(16) char SMB[33792];
    bf16* SM = (bf16*)SMB;
    float* Cst = (float*)SMB;

    const bf16 *Wh, *Wl, *Xh, *Xl;
    const float* bias;
    bf16 *Qh_, *Ql_, *Kh_, *Kl_, *Vh_, *Vl_;
    int N, K, m0, n0, b;
    int blk = blockIdx.x;
    if (blk < 96) {
        N = HWY; K = Y_CH;
        b = blk / 48; int r = blk % 48; m0 = (r % 3) * 128; n0 = (r / 3) * 64;
        Wh = g_wyqh; Wl = g_wyql;
        Xh = g_ysh + (size_t)b * K * N; Xl = g_ysl + (size_t)b * K * N;
        bias = by_;
        Qh_=g_qyh; Ql_=g_qyl; Kh_=g_kyh; Kl_=g_kyl; Vh_=g_vyh; Vl_=g_vyl;
    } else {
        blk -= 96;
        N = HWX; K = X_CH;
        b = blk / 192; int r = blk % 192; m0 = (r % 3) * 128; n0 = (r / 3) * 64;
        Wh = g_wxqh; Wl = g_wxql;
        Xh = g_xsh + (size_t)b * K * N; Xl = g_xsl + (size_t)b * K * N;
        bias = bx;
        Qh_=g_qxh; Ql_=g_qxl; Kh_=g_kxh; Kl_=g_kxl; Vh_=g_vxh; Vl_=g_vxl;
    }

    const int tid = threadIdx.x, lane = tid & 31;
    const int w = tid >> 5;
    const int wm = w & 3, wn = w >> 2;
    const int arow = (lane & 7) + ((lane & 8) ? 8 : 0);
    const int acol = (lane & 16) ? 8 : 0;
    const int bkrow = (lane & 7) + ((lane & 8) ? 8 : 0);
    const int bncol = (lane & 16) ? 8 : 0;

    const unsigned sbase = (unsigned)__cvta_generic_to_shared(SMB);

    auto fill = [&](int s, int kc) {
        #pragma unroll
        for (int it = 0; it < 3; it++) {
            int id = tid + it * 256;
            if (id < 512) {
                int part = id & 1, rid = id >> 1;
                int row = rid >> 1, cc = rid & 1;
                unsigned adst = sbase + (unsigned)(s*ST_TOT5 + part*ST_A + row*ASTR + cc*8) * 2;
                cpasync16(adst, (part ? Wl : Wh) + (size_t)(m0 + row) * K + kc*16 + cc*8);
            } else {
                int j = id - 512;
                int part = j & 1, rid2 = j >> 1;
                int krow = rid2 >> 3, nc = rid2 & 7;
                unsigned bdst = sbase + (unsigned)(s*ST_TOT5 + 2*ST_A + part*ST_B5 + krow*BSTR5 + nc*8) * 2;
                cpasync16(bdst, (part ? Xl : Xh) + (size_t)(kc*16 + krow) * N + n0 + nc*8);
            }
        }
        asm volatile("cp.async.commit_group;");
    };

    float acc[2][4][4] = {};
    const int nkc = K >> 4;

    fill(0, 0);
    for (int kc = 0; kc < nkc; kc++) {
        const int s = kc & 1;
        if (kc + 1 < nkc) {
            fill(s ^ 1, kc + 1);
            asm volatile("cp.async.wait_group 1;" ::: "memory");
        } else {
            asm volatile("cp.async.wait_group 0;" ::: "memory");
        }
        __syncthreads();

        const bf16* Ah = SM + s*ST_TOT5;
        const bf16* Al = Ah + ST_A;
        const bf16* Bh = SM + s*ST_TOT5 + 2*ST_A;
        const bf16* Bl = Bh + ST_B5;

        unsigned ah[2][4], al[2][4];
        #pragma unroll
        for (int im = 0; im < 2; im++) {
            ldsm4(ah[im], &Ah[(wm*32 + im*16 + arow) * ASTR + acol]);
            ldsm4(al[im], &Al[(wm*32 + im*16 + arow) * ASTR + acol]);
        }
        #pragma unroll
        for (int jn = 0; jn < 2; jn++) {
            unsigned bh4[4], bl4[4];
            const int boff = bkrow * BSTR5 + wn*32 + jn*16 + bncol;
            ldsm4t(bh4, &Bh[boff]);
            ldsm4t(bl4, &Bl[boff]);
            #pragma unroll
            for (int im = 0; im < 2; im++) {
                mma16816(acc[im][2*jn],   ah[im], bh4[0], bh4[1]);
                mma16816(acc[im][2*jn],   al[im], bh4[0], bh4[1]);
                mma16816(acc[im][2*jn],   ah[im], bl4[0], bl4[1]);
                mma16816(acc[im][2*jn+1], ah[im], bh4[2], bh4[3]);
                mma16816(acc[im][2*jn+1], al[im], bh4[2], bh4[3]);
                mma16816(acc[im][2*jn+1], ah[im], bl4[2], bl4[3]);
            }
        }
        __syncthreads();
    }

    const int r = lane >> 2, cq = (lane & 3) * 2;
    #pragma unroll
    for (int im = 0; im < 2; im++) {
        __syncthreads();
        #pragma unroll
        for (int j8 = 0; j8 < 4; j8++) {
            int col = wn*32 + j8*8 + cq;
            Cst[(wm*16 + r) * 64 + col]         = acc[im][j8][0];
            Cst[(wm*16 + r) * 64 + col + 1]     = acc[im][j8][1];
            Cst[(wm*16 + r + 8) * 64 + col]     = acc[im][j8][2];
            Cst[(wm*16 + r + 8) * 64 + col + 1] = acc[im][j8][3];
        }
        __syncthreads();
        for (int idx = tid; idx < 64*64; idx += 256) {
            int srow = idx >> 6, scol = idx & 63;
            int o = m0 + (srow >> 4) * 32 + im*16 + (srow & 15);
            int n = n0 + scol;
            float v = Cst[idx] + bias[o];
            int t = o >> 7, h = (o & 127) >> 5, d = o & 31;
            bf16 hh, ll;
            if (t == 0) {
                bsplit(v * GAMMA_L2E, hh, ll);
                size_t i2 = ((size_t)(b*NHEAD + h) * N + n) * HD + d;
                Qh_[i2] = hh;  Ql_[i2] = ll;
            } else if (t == 1) {
                bsplit(v, hh, ll);
                size_t i2 = ((size_t)(b*NHEAD + h) * N + n) * HD + d;
                Kh_[i2] = hh;  Kl_[i2] = ll;
            } else {
                bsplit(v, hh, ll);
                size_t i2 = ((size_t)(b*NHEAD + h) * HD + d) * N + n;
                Vh_[i2] = hh;  Vl_[i2] = ll;
            }
        }
    }
}

// ====== proj tensor-core GEMM (validated round-14) =========================
__global__ void __launch_bounds__(256) proj_mma_kernel(
    const float* __restrict__ bpx, const float* __restrict__ Rx,
    const float* __restrict__ bpy, const float* __restrict__ Ry,
    float* __restrict__ outp)
{
    __shared__ __align__(16) char SMB[33792];
    bf16* SM = (bf16*)SMB;
    float* Cst = (float*)SMB;

    const bf16 *Wh, *Wl, *Xh, *Xl;
    const float *bias, *Res;
    float* Out;
    int N, OC, m0, n0, b;
    int blk = blockIdx.x;
    if (blk < 128) {
        N = HWY; OC = Y_CH;
        b = blk / 64; int r = blk % 64; m0 = (r % 4) * 128; n0 = (r / 4) * 64;
        Wh = g_wpyh; Wl = g_wpyl;
        Xh = g_ayh + (size_t)b * DIM * N; Xl = g_ayl + (size_t)b * DIM * N;
        bias = bpy; Res = Ry; Out = outp + (size_t)BATCH * X_CH * HWX;
    } else {
        blk -= 128;
        N = HWX; OC = X_CH;
        b = blk / 128; int r = blk % 128; m0 = (r % 2) * 128; n0 = (r / 2) * 64;
        Wh = g_wpxh; Wl = g_wpxl;
        Xh = g_axh + (size_t)b * DIM * N; Xl = g_axl + (size_t)b * DIM * N;
        bias = bpx; Res = Rx; Out = outp;
    }
    const int K = DIM;

    const int tid = threadIdx.x, lane = tid & 31;
    const int w = tid >> 5;
    const int wm = w & 3, wn = w >> 2;
    const int arow = (lane & 7) + ((lane & 8) ? 8 : 0);
    const int acol = (lane & 16) ? 8 : 0;
    const int bkrow = (lane & 7) + ((lane & 8) ? 8 : 0);
    const int bncol = (lane & 16) ? 8 : 0;

    const unsigned sbase = (unsigned)__cvta_generic_to_shared(SMB);

    auto fill = [&](int s, int kc) {
        #pragma unroll
        for (int it = 0; it < 3; it++) {
            int id = tid + it * 256;
            if (id < 512) {
                int part = id & 1, rid = id >> 1;
                int row = rid >> 1, cc = rid & 1;
                unsigned adst = sbase + (unsigned)(s*ST_TOT5 + part*ST_A + row*ASTR + cc*8) * 2;
                cpasync16(adst, (part ? Wl : Wh) + (size_t)(m0 + row) * K + kc*16 + cc*8);
            } else {
                int j = id - 512;
                int part = j & 1, rid2 = j >> 1;
                int krow = rid2 >> 3, nc = rid2 & 7;
                unsigned bdst = sbase + (unsigned)(s*ST_TOT5 + 2*ST_A + part*ST_B5 + krow*BSTR5 + nc*8) * 2;
                cpasync16(bdst, (part ? Xl : Xh) + (size_t)(kc*16 + krow) * N + n0 + nc*8);
            }
        }
        asm volatile("cp.async.commit_group;");
    };

    float acc[2][4][4] = {};
    const int nkc = K >> 4;

    fill(0, 0);
    for (int kc = 0; kc < nkc; kc++) {
        const int s = kc & 1;
        if (kc + 1 < nkc) {
            fill(s ^ 1, kc + 1);
            asm volatile("cp.async.wait_group 1;" ::: "memory");
        } else {
            asm volatile("cp.async.wait_group 0;" ::: "memory");
        }
        __syncthreads();

        const bf16* Ah = SM + s*ST_TOT5;
        const bf16* Al = Ah + ST_A;
        const bf16* Bh = SM + s*ST_TOT5 + 2*ST_A;
        const bf16* Bl = Bh + ST_B5;

        unsigned ah[2][4], al[2][4];
        #pragma unroll
        for (int im = 0; im < 2; im++) {
            ldsm4(ah[im], &Ah[(wm*32 + im*16 + arow) * ASTR + acol]);
            ldsm4(al[im], &Al[(wm*32 + im*16 + arow) * ASTR + acol]);
        }
        #pragma unroll
        for (int jn = 0; jn < 2; jn++) {
            unsigned bh4[4], bl4[4];
            const int boff = bkrow * BSTR5 + wn*32 + jn*16 + bncol;
            ldsm4t(bh4, &Bh[boff]);
            ldsm4t(bl4, &Bl[boff]);
            #pragma unroll
            for (int im = 0; im < 2; im++) {
                mma16816(acc[im][2*jn],   ah[im], bh4[0], bh4[1]);
                mma16816(acc[im][2*jn],   al[im], bh4[0], bh4[1]);
                mma16816(acc[im][2*jn],   ah[im], bl4[0], bl4[1]);
                mma16816(acc[im][2*jn+1], ah[im], bh4[2], bh4[3]);
                mma16816(acc[im][2*jn+1], al[im], bh4[2], bh4[3]);
                mma16816(acc[im][2*jn+1], ah[im], bl4[2], bl4[3]);
            }
        }
        __syncthreads();
    }

    const int r = lane >> 2, cq = (lane & 3) * 2;
    #pragma unroll
    for (int im = 0; im < 2; im++) {
        __syncthreads();
        #pragma unroll
        for (int j8 = 0; j8 < 4; j8++) {
            int col = wn*32 + j8*8 + cq;
            Cst[(wm*16 + r) * 64 + col]         = acc[im][j8][0];
            Cst[(wm*16 + r) * 64 + col + 1]     = acc[im][j8][1];
            Cst[(wm*16 + r + 8) * 64 + col]     = acc[im][j8][2];
            Cst[(wm*16 + r + 8) * 64 + col + 1] = acc[im][j8][3];
        }
        __syncthreads();
        for (int idx = tid; idx < 64*64; idx += 256) {
            int srow = idx >> 6, scol = idx & 63;
            int o = m0 + (srow >> 4) * 32 + im*16 + (srow & 15);
            int n = n0 + scol;
            size_t off = ((size_t)b * OC + o) * N + n;
            Out[off] = Cst[idx] + bias[o] + Res[off];
        }
    }
}

// ====== MMA flash attention v3: 8 warps / 128q per block ===================
#define QSTR 40
#define VSTR 72
#define OFF_KH 0
#define OFF_KL 2560
#define OFF_VH 5120
#define OFF_VL 7424
#define STAGE_ELEMS 9728

// blocks [0,256): dir1 = 8bh x 8 qtiles(128q) x 4 splits (16 tiles each).
// blocks [256,512): dir0 = 8bh x 32 qtiles (16 tiles each).
__global__ void __launch_bounds__(256) attn_mma_kernel()
{
    __shared__ __align__(16) bf16 KV[2][STAGE_ELEMS];

    int blk = blockIdx.x;
    const bf16 *Qh, *Ql, *Kh, *Kl, *Vh, *Vl;
    bf16 *Oh_ = nullptr, *Ol_ = nullptr;
    int NQ, NK, bh, q0, kt0, sp = 0;
    bool split;
    if (blk < 256) {   // dir1: y attends x, 4-way split-K
        split = true;
        bh = blk >> 5;                 // 0..7
        int r2 = blk & 31;
        q0 = (r2 >> 2) * 128;          // 8 q-tiles of 128
        sp = r2 & 3;
        kt0 = sp * 16;
        NQ = HWY; NK = HWX;
        Qh=g_qyh; Ql=g_qyl; Kh=g_kxh; Kl=g_kxl; Vh=g_vxh; Vl=g_vxl;
    } else {           // dir0: x attends y
        split = false;
        blk -= 256;
        bh = blk >> 5; q0 = (blk & 31) * 128; kt0 = 0; NQ = HWX; NK = HWY;
        Qh=g_qxh; Ql=g_qxl; Kh=g_kyh; Kl=g_kyl; Vh=g_vyh; Vl=g_vyl;
        Oh_ = g_axh; Ol_ = g_axl;
    }
    const int nt = 16;

    const int tid = threadIdx.x, w = tid >> 5, lane = tid & 31;
    const size_t kbase = (size_t)bh * NK * HD;
    const size_t vbase = (size_t)bh * HD * NK;

    // one 8-elem chunk per thread per buffer (256 threads x 8 = 2048 elems)
    const int e0 = tid * 8;
    const int ks0 = (e0 >> 5) * QSTR + (e0 & 31);
    const int vs0 = (e0 >> 6) * VSTR + (e0 & 63);
    const size_t kg0 = (size_t)(e0 >> 5) * HD + (e0 & 31);
    const size_t vg0 = (size_t)(e0 >> 6) * NK + (e0 & 63);

    unsigned sb0 = (unsigned)__cvta_generic_to_shared(&KV[0][0]);
    unsigned sb1 = (unsigned)__cvta_generic_to_shared(&KV[1][0]);

    {   // issue tile kt0 into stage 0
        size_t ka = kbase + (size_t)kt0 * 64 * HD;
        size_t va = vbase + (size_t)kt0 * 64;
        cpasync16(sb0 + (OFF_KH + ks0) * 2, Kh + ka + kg0);
        cpasync16(sb0 + (OFF_KL + ks0) * 2, Kl + ka + kg0);
        cpasync16(sb0 + (OFF_VH + vs0) * 2, Vh + va + vg0);
        cpasync16(sb0 + (OFF_VL + vs0) * 2, Vl + va + vg0);
        asm volatile("cp.async.commit_group;");
    }

    // Q fragments direct from global (one-time; lane map validated round-8)
    unsigned qf[2][2][4];
    {
        const size_t qrow = (size_t)bh * NQ * HD + (size_t)(q0 + w*16 + (lane >> 2)) * HD;
        const int qc = (lane & 3) * 2;
        #pragma unroll
        for (int p = 0; p < 2; p++) {
            const bf16* Qp = p ? Ql : Qh;
            #pragma unroll
            for (int c = 0; c < 2; c++) {
                const bf16* base = Qp + qrow + c*16 + qc;
                qf[p][c][0] = *(const unsigned*)(base);
                qf[p][c][1] = *(const unsigned*)(base + 8*HD);
                qf[p][c][2] = *(const unsigned*)(base + 8);
                qf[p][c][3] = *(const unsigned*)(base + 8*HD + 8);
            }
        }
    }

    const int brow = (lane & 7) + ((lane & 16) ? 8 : 0);
    const int bcol = (lane & 8) ? 8 : 0;

    float m0r = -1e30f, m1r = -1e30f, l0 = 0.f, l1 = 0.f;
    float oacc[4][4] = {};

    for (int i = 0; i < nt; i++) {
        const int s = i & 1;
        if (i + 1 < nt) {
            unsigned sb = (s ^ 1) ? sb1 : sb0;
            size_t ka = kbase + (size_t)(kt0 + i + 1) * 64 * HD;
            size_t va = vbase + (size_t)(kt0 + i + 1) * 64;
            cpasync16(sb + (OFF_KH + ks0) * 2, Kh + ka + kg0);
            cpasync16(sb + (OFF_KL + ks0) * 2, Kl + ka + kg0);
            cpasync16(sb + (OFF_VH + vs0) * 2, Vh + va + vg0);
            cpasync16(sb + (OFF_VL + vs0) * 2, Vl + va + vg0);
            asm volatile("cp.async.commit_group;");
            asm volatile("cp.async.wait_group 1;" ::: "memory");
        } else {
            asm volatile("cp.async.wait_group 0;" ::: "memory");
        }
        __syncthreads();

        const bf16* Ks0 = &KV[s][OFF_KH];
        const bf16* Ks1 = &KV[s][OFF_KL];
        const bf16* Vs0 = &KV[s][OFF_VH];
        const bf16* Vs1 = &KV[s][OFF_VL];

        float sreg[8][4];
        #pragma unroll
        for (int nb = 0; nb < 8; nb++)
            sreg[nb][0] = sreg[nb][1] = sreg[nb][2] = sreg[nb][3] = 0.f;

        #pragma unroll
        for (int c = 0; c < 2; c++) {
            #pragma unroll
            for (int jp = 0; jp < 4; jp++) {
                unsigned kh4[4], kl4[4];
                ldsm4(kh4, &Ks0[(jp * 16 + brow) * QSTR + c * 16 + bcol]);
                ldsm4(kl4, &Ks1[(jp * 16 + brow) * QSTR + c * 16 + bcol]);
                mma16816(sreg[2*jp],   qf[0][c], kh4[0], kh4[1]);
                mma16816(sreg[2*jp],   qf[1][c], kh4[0], kh4[1]);
                mma16816(sreg[2*jp],   qf[0][c], kl4[0], kl4[1]);
                mma16816(sreg[2*jp+1], qf[0][c], kh4[2], kh4[3]);
                mma16816(sreg[2*jp+1], qf[1][c], kh4[2], kh4[3]);
                mma16816(sreg[2*jp+1], qf[0][c], kl4[2], kl4[3]);
            }
        }

        float mx0 = sreg[0][0], mx1 = sreg[0][2];
        #pragma unroll
        for (int nb = 0; nb < 8; nb++) {
            mx0 = fmaxf(mx0, fmaxf(sreg[nb][0], sreg[nb][1]));
            mx1 = fmaxf(mx1, fmaxf(sreg[nb][2], sreg[nb][3]));
        }
        mx0 = fmaxf(mx0, __shfl_xor_sync(~0u, mx0, 1));
        mx0 = fmaxf(mx0, __shfl_xor_sync(~0u, mx0, 2));
        mx1 = fmaxf(mx1, __shfl_xor_sync(~0u, mx1, 1));
        mx1 = fmaxf(mx1, __shfl_xor_sync(~0u, mx1, 2));
        float nm0 = fmaxf(m0r, mx0), nm1 = fmaxf(m1r, mx1);
        float sc0 = exp2f(m0r - nm0), sc1 = exp2f(m1r - nm1);
        m0r = nm0; m1r = nm1;
        float rs0 = 0.f, rs1 = 0.f;
        #pragma unroll
        for (int nb = 0; nb < 8; nb++) {
            sreg[nb][0] = exp2f(sreg[nb][0] - nm0);
            sreg[nb][1] = exp2f(sreg[nb][1] - nm0);
            sreg[nb][2] = exp2f(sreg[nb][2] - nm1);
            sreg[nb][3] = exp2f(sreg[nb][3] - nm1);
            rs0 += sreg[nb][0] + sreg[nb][1];
            rs1 += sreg[nb][2] + sreg[nb][3];
        }
        rs0 += __shfl_xor_sync(~0u, rs0, 1);
        rs0 += __shfl_xor_sync(~0u, rs0, 2);
        rs1 += __shfl_xor_sync(~0u, rs1, 1);
        rs1 += __shfl_xor_sync(~0u, rs1, 2);
        l0 = l0 * sc0 + rs0;  l1 = l1 * sc1 + rs1;
        #pragma unroll
        for (int nb = 0; nb < 4; nb++) {
            oacc[nb][0] *= sc0; oacc[nb][1] *= sc0;
            oacc[nb][2] *= sc1; oacc[nb][3] *= sc1;
        }

        #pragma unroll
        for (int c = 0; c < 4; c++) {
            unsigned pah[4], pal[4];
            #pragma unroll
            for (int r4 = 0; r4 < 4; r4++) {
                int nb = 2 * c + (r4 >> 1);
                int pr = (r4 & 1) * 2;
                psplit2(sreg[nb][pr], sreg[nb][pr + 1], pah[r4], pal[r4]);
            }
            #pragma unroll
            for (int np = 0; np < 2; np++) {
                unsigned vh4[4], vl4[4];
                ldsm4(vh4, &Vs0[(np * 16 + brow) * VSTR + c * 16 + bcol]);
                ldsm4(vl4, &Vs1[(np * 16 + brow) * VSTR + c * 16 + bcol]);
                mma16816(oacc[2*np],   pah, vh4[0], vh4[1]);
                mma16816(oacc[2*np],   pal, vh4[0], vh4[1]);
                mma16816(oacc[2*np],   pah, vl4[0], vl4[1]);
                mma16816(oacc[2*np+1], pah, vh4[2], vh4[3]);
                mma16816(oacc[2*np+1], pal, vh4[2], vh4[3]);
                mma16816(oacc[2*np+1], pah, vl4[2], vl4[3]);
            }
        }
        __syncthreads();
    }

    int r = lane >> 2;
    int qg = q0 + w * 16 + r;
    if (split) {
        size_t pb = ((size_t)sp * 8 + bh) * HWY;
        #pragma unroll
        for (int nb = 0; nb < 4; nb++) {
            int d = nb * 8 + (lane & 3) * 2;
            *(float2*)&g_pacc[(pb + qg) * HD + d]     = make_float2(oacc[nb][0], oacc[nb][1]);
            *(float2*)&g_pacc[(pb + qg + 8) * HD + d] = make_float2(oacc[nb][2], oacc[nb][3]);
        }
        if ((lane & 3) == 0) {
            g_pml[pb + qg]     = make_float2(m0r, l0);
            g_pml[pb + qg + 8] = make_float2(m1r, l1);
        }
    } else {
        // write split bf16, TRANSPOSED [bh][d][q]
        float inv0 = 1.f / l0, inv1 = 1.f / l1;
        size_t ob = (size_t)bh * HD * NQ;
        #pragma unroll
        for (int nb = 0; nb < 4; nb++) {
            int d = nb * 8 + (lane & 3) * 2;
            bf16 hh, ll;
            bsplit(oacc[nb][0] * inv0, hh, ll);
            Oh_[ob + (size_t)d * NQ + qg] = hh;       Ol_[ob + (size_t)d * NQ + qg] = ll;
            bsplit(oacc[nb][1] * inv0, hh, ll);
            Oh_[ob + (size_t)(d+1) * NQ + qg] = hh;   Ol_[ob + (size_t)(d+1) * NQ + qg] = ll;
            bsplit(oacc[nb][2] * inv1, hh, ll);
            Oh_[ob + (size_t)d * NQ + qg + 8] = hh;   Ol_[ob + (size_t)d * NQ + qg + 8] = ll;
            bsplit(oacc[nb][3] * inv1, hh, ll);
            Oh_[ob + (size_t)(d+1) * NQ + qg + 8] = hh; Ol_[ob + (size_t)(d+1) * NQ + qg + 8] = ll;
        }
    }
}

// ====== combine split-K partials (validated round-14) ======================
__global__ void __launch_bounds__(128) attn_combine_kernel()
{
    int t = blockIdx.x * 128 + threadIdx.x;
    int bh = t >> 10, q = t & 1023;
    float2 ml[4];
    float M = -1e30f;
    #pragma unroll
    for (int s = 0; s < 4; s++) {
        ml[s] = g_pml[((size_t)s * 8 + bh) * HWY + q];
        M = fmaxf(M, ml[s].x);
    }
    float wgt[4], L = 0.f;
    #pragma unroll
    for (int s = 0; s < 4; s++) {
        wgt[s] = exp2f(ml[s].x - M);
        L += wgt[s] * ml[s].y;
    }
    float invL = 1.f / L;
    size_t ob = (size_t)bh * HD * HWY;
    #pragma unroll
    for (int d4 = 0; d4 < HD; d4 += 4) {
        float4 o = make_float4(0.f, 0.f, 0.f, 0.f);
        #pragma unroll
        for (int s = 0; s < 4; s++) {
            const float* a = g_pacc + (((size_t)s * 8 + bh) * HWY + q) * HD;
            float4 v = *(const float4*)(a + d4);
            o.x += wgt[s] * v.x;  o.y += wgt[s] * v.y;
            o.z += wgt[s] * v.z;  o.w += wgt[s] * v.w;
        }
        float vals[4] = {o.x * invL, o.y * invL, o.z * invL, o.w * invL};
        #pragma unroll
        for (int j = 0; j < 4; j++) {
            bf16 hh, ll; bsplit(vals[j], hh, ll);
            g_ayh[ob + (size_t)(d4 + j) * HWY + q] = hh;
            g_ayl[ob + (size_t)(d4 + j) * HWY + q] = ll;
        }
    }
}

// ============================== launcher ==================================
extern "C" void kernel_launch(void* const* d_in, const int* in_sizes, int n_in,
                              void* d_out, int out_size)
{
    (void)out_size;
    const float *x=0, *y=0, *wxq=0, *bxq=0, *wyq=0, *byq=0,
                *wpx=0, *bpx=0, *wpy=0, *bpy=0;
    for (int i = 0; i < n_in; i++) {
        const float* p = (const float*)d_in[i];
        switch (in_sizes[i]) {
            case 2097152: x = p;   break;
            case 1048576: y = p;   break;
            case 98304:   wxq = p; break;
            case 196608:  wyq = p; break;
            case 32768:   wpx = p; break;
            case 65536:   wpy = p; break;
            case 256:     bpx = p; break;
            case 512:     bpy = p; break;
            case 384:     if (!bxq) bxq = p; else byq = p; break;
            default: break;
        }
    }
    float* out = (float*)d_out;

    split_w_kernel<<<384, 256>>>(wxq, wyq, wpx, wpy);
    presplit_x_kernel<<<3072, 256>>>(x, y);
    qkv_mma5_kernel<<<480, 256>>>(bxq, byq);
    attn_mma_kernel<<<512, 256>>>();
    attn_combine_kernel<<<64, 128>>>();
    proj_mma_kernel<<<384, 256>>>(bpx, x, bpy, y, out);
}

// round 17
// speedup vs baseline: 1.3621x; 1.2793x over previous
#include <cuda_runtime.h>
#include <cuda_bf16.h>

#define X_CH   256
#define Y_CH   512
#define DIM    128
#define NHEAD  4
#define HD     32
#define HWX    4096
#define HWY    1024
#define BATCH  2
#define GAMMA  0.17677669529663687f
#define GAMMA_L2E (0.17677669529663687f * 1.4426950408889634f)

typedef __nv_bfloat16 bf16;

// ---------------- scratch (device globals; no allocation) ----------------
static __device__ __align__(16) bf16 g_qxh[BATCH*NHEAD*HWX*HD], g_qxl[BATCH*NHEAD*HWX*HD];
static __device__ __align__(16) bf16 g_kxh[BATCH*NHEAD*HWX*HD], g_kxl[BATCH*NHEAD*HWX*HD];
static __device__ __align__(16) bf16 g_vxh[BATCH*NHEAD*HWX*HD], g_vxl[BATCH*NHEAD*HWX*HD];
static __device__ __align__(16) bf16 g_qyh[BATCH*NHEAD*HWY*HD], g_qyl[BATCH*NHEAD*HWY*HD];
static __device__ __align__(16) bf16 g_kyh[BATCH*NHEAD*HWY*HD], g_kyl[BATCH*NHEAD*HWY*HD];
static __device__ __align__(16) bf16 g_vyh[BATCH*NHEAD*HWY*HD], g_vyl[BATCH*NHEAD*HWY*HD];
// attention out, split bf16, TRANSPOSED [b, c=h*32+d, q]
static __device__ __align__(16) bf16 g_axh[BATCH*DIM*HWX], g_axl[BATCH*DIM*HWX];
static __device__ __align__(16) bf16 g_ayh[BATCH*DIM*HWY], g_ayl[BATCH*DIM*HWY];
// pre-split weights [M][K] and inputs [B][C][N]
static __device__ __align__(16) bf16 g_wxqh[384*X_CH], g_wxql[384*X_CH];
static __device__ __align__(16) bf16 g_wyqh[384*Y_CH], g_wyql[384*Y_CH];
static __device__ __align__(16) bf16 g_wpxh[X_CH*DIM], g_wpxl[X_CH*DIM];
static __device__ __align__(16) bf16 g_wpyh[Y_CH*DIM], g_wpyl[Y_CH*DIM];
static __device__ __align__(16) bf16 g_xsh[BATCH*X_CH*HWX], g_xsl[BATCH*X_CH*HWX];
static __device__ __align__(16) bf16 g_ysh[BATCH*Y_CH*HWY], g_ysl[BATCH*Y_CH*HWY];
// split-K partials for dir1
static __device__ __align__(16) float  g_pacc[4*BATCH*NHEAD*HWY*HD];
static __device__ __align__(16) float2 g_pml[4*BATCH*NHEAD*HWY];

__device__ __forceinline__ void bsplit(float v, bf16& h, bf16& l) {
    h = __float2bfloat16(v);
    l = __float2bfloat16(v - __bfloat162float(h));
}
__device__ __forceinline__ unsigned pack2(bf16 a, bf16 b) {
    return (unsigned)__bfloat16_as_ushort(a) | ((unsigned)__bfloat16_as_ushort(b) << 16);
}
__device__ __forceinline__ void psplit2(float x0, float x1, unsigned& ph, unsigned& pl) {
    unsigned h;
    asm("cvt.rn.bf16x2.f32 %0, %1, %2;" : "=r"(h) : "f"(x1), "f"(x0));
    float h0 = __uint_as_float(h << 16);
    float h1 = __uint_as_float(h & 0xffff0000u);
    float e0 = x0 - h0, e1 = x1 - h1;
    asm("cvt.rn.bf16x2.f32 %0, %1, %2;" : "=r"(pl) : "f"(e1), "f"(e0));
    ph = h;
}

// ---------------- prep: split all 4 weight matrices (validated) -----------
__global__ void __launch_bounds__(256) split_w_kernel(
    const float* __restrict__ s0, const float* __restrict__ s1,
    const float* __restrict__ s2, const float* __restrict__ s3)
{
    int e = (blockIdx.x * 256 + threadIdx.x) * 4;
    const float* s; bf16 *dh, *dl;
    if (e < 98304)       { s = s0; dh = g_wxqh; dl = g_wxql; }
    else if (e < 294912) { e -= 98304;  s = s1; dh = g_wyqh; dl = g_wyql; }
    else if (e < 327680) { e -= 294912; s = s2; dh = g_wpxh; dl = g_wpxl; }
    else                 { e -= 327680; s = s3; dh = g_wpyh; dl = g_wpyl; }
    float4 v = *(const float4*)(s + e);
    bf16 h0,l0,h1,l1,h2,l2,h3,l3;
    bsplit(v.x,h0,l0); bsplit(v.y,h1,l1); bsplit(v.z,h2,l2); bsplit(v.w,h3,l3);
    *(uint2*)(dh + e) = make_uint2(pack2(h0,h1), pack2(h2,h3));
    *(uint2*)(dl + e) = make_uint2(pack2(l0,l1), pack2(l2,l3));
}

// ---------------- prep: split inputs elementwise (validated) ----------
__global__ void __launch_bounds__(256) presplit_x_kernel(
    const float* __restrict__ x, const float* __restrict__ y)
{
    int e = (blockIdx.x * 256 + threadIdx.x) * 4;
    const float* s; bf16 *dh, *dl;
    if (e < BATCH*X_CH*HWX) { s = x; dh = g_xsh; dl = g_xsl; }
    else { e -= BATCH*X_CH*HWX; s = y; dh = g_ysh; dl = g_ysl; }
    float4 v = *(const float4*)(s + e);
    bf16 h0,l0,h1,l1,h2,l2,h3,l3;
    bsplit(v.x,h0,l0); bsplit(v.y,h1,l1); bsplit(v.z,h2,l2); bsplit(v.w,h3,l3);
    *(uint2*)(dh + e) = make_uint2(pack2(h0,h1), pack2(h2,h3));
    *(uint2*)(dl + e) = make_uint2(pack2(l0,l1), pack2(l2,l3));
}

// ---------------- MMA helpers ----------------
__device__ __forceinline__ void ldsm4(unsigned r[4], const void* p) {
    unsigned a = (unsigned)__cvta_generic_to_shared(p);
    asm volatile("ldmatrix.sync.aligned.m8n8.x4.shared.b16 {%0,%1,%2,%3}, [%4];"
        : "=r"(r[0]), "=r"(r[1]), "=r"(r[2]), "=r"(r[3]) : "r"(a));
}
__device__ __forceinline__ void ldsm4t(unsigned r[4], const void* p) {
    unsigned a = (unsigned)__cvta_generic_to_shared(p);
    asm volatile("ldmatrix.sync.aligned.m8n8.x4.trans.shared.b16 {%0,%1,%2,%3}, [%4];"
        : "=r"(r[0]), "=r"(r[1]), "=r"(r[2]), "=r"(r[3]) : "r"(a));
}
__device__ __forceinline__ void mma16816(float c[4], const unsigned a[4],
                                         unsigned b0, unsigned b1) {
    asm volatile("mma.sync.aligned.m16n8k16.row.col.f32.bf16.bf16.f32 "
        "{%0,%1,%2,%3}, {%4,%5,%6,%7}, {%8,%9}, {%0,%1,%2,%3};"
        : "+f"(c[0]), "+f"(c[1]), "+f"(c[2]), "+f"(c[3])
        : "r"(a[0]), "r"(a[1]), "r"(a[2]), "r"(a[3]), "r"(b0), "r"(b1));
}
__device__ __forceinline__ void cpasync16(unsigned dst, const void* src) {
    asm volatile("cp.async.ca.shared.global [%0], [%1], 16;" :: "r"(dst), "l"(src));
}

// ====== shared GEMM geometry (v5 template, validated) ============
#define ASTR 24
#define BSTR5 72
#define ST_A 3072
#define ST_B5 1152
#define ST_TOT5 8448

// ====== QKV tensor-core GEMM v5 + coalesced Q/K epilogue ==================
// blocks [0,96): y (2b x 3m x 16n); [96,480): x (2b x 3m x 64n)
// m0 = 0 -> Q block, 128 -> K block, 256 -> V block (t constant per block).
__global__ void __launch_bounds__(256) qkv_mma5_kernel(
    const float* __restrict__ bx, const float* __restrict__ by_)
{
    __shared__ __align__(16) char SMB[33792];
    bf16* SM = (bf16*)SMB;
    float* Cst = (float*)SMB;

    const bf16 *Wh, *Wl, *Xh, *Xl;
    const float* bias;
    bf16 *Qh_, *Ql_, *Kh_, *Kl_, *Vh_, *Vl_;
    int N, K, m0, n0, b;
    int blk = blockIdx.x;
    if (blk < 96) {
        N = HWY; K = Y_CH;
        b = blk / 48; int r = blk % 48; m0 = (r % 3) * 128; n0 = (r / 3) * 64;
        Wh = g_wyqh; Wl = g_wyql;
        Xh = g_ysh + (size_t)b * K * N; Xl = g_ysl + (size_t)b * K * N;
        bias = by_;
        Qh_=g_qyh; Ql_=g_qyl; Kh_=g_kyh; Kl_=g_kyl; Vh_=g_vyh; Vl_=g_vyl;
    } else {
        blk -= 96;
        N = HWX; K = X_CH;
        b = blk / 192; int r = blk % 192; m0 = (r % 3) * 128; n0 = (r / 3) * 64;
        Wh = g_wxqh; Wl = g_wxql;
        Xh = g_xsh + (size_t)b * K * N; Xl = g_xsl + (size_t)b * K * N;
        bias = bx;
        Qh_=g_qxh; Ql_=g_qxl; Kh_=g_kxh; Kl_=g_kxl; Vh_=g_vxh; Vl_=g_vxl;
    }

    const int tid = threadIdx.x, lane = tid & 31;
    const int w = tid >> 5;
    const int wm = w & 3, wn = w >> 2;
    const int arow = (lane & 7) + ((lane & 8) ? 8 : 0);
    const int acol = (lane & 16) ? 8 : 0;
    const int bkrow = (lane & 7) + ((lane & 8) ? 8 : 0);
    const int bncol = (lane & 16) ? 8 : 0;

    const unsigned sbase = (unsigned)__cvta_generic_to_shared(SMB);

    auto fill = [&](int s, int kc) {
        #pragma unroll
        for (int it = 0; it < 3; it++) {
            int id = tid + it * 256;
            if (id < 512) {
                int part = id & 1, rid = id >> 1;
                int row = rid >> 1, cc = rid & 1;
                unsigned adst = sbase + (unsigned)(s*ST_TOT5 + part*ST_A + row*ASTR + cc*8) * 2;
                cpasync16(adst, (part ? Wl : Wh) + (size_t)(m0 + row) * K + kc*16 + cc*8);
            } else {
                int j = id - 512;
                int part = j & 1, rid2 = j >> 1;
                int krow = rid2 >> 3, nc = rid2 & 7;
                unsigned bdst = sbase + (unsigned)(s*ST_TOT5 + 2*ST_A + part*ST_B5 + krow*BSTR5 + nc*8) * 2;
                cpasync16(bdst, (part ? Xl : Xh) + (size_t)(kc*16 + krow) * N + n0 + nc*8);
            }
        }
        asm volatile("cp.async.commit_group;");
    };

    float acc[2][4][4] = {};
    const int nkc = K >> 4;

    fill(0, 0);
    for (int kc = 0; kc < nkc; kc++) {
        const int s = kc & 1;
        if (kc + 1 < nkc) {
            fill(s ^ 1, kc + 1);
            asm volatile("cp.async.wait_group 1;" ::: "memory");
        } else {
            asm volatile("cp.async.wait_group 0;" ::: "memory");
        }
        __syncthreads();

        const bf16* Ah = SM + s*ST_TOT5;
        const bf16* Al = Ah + ST_A;
        const bf16* Bh = SM + s*ST_TOT5 + 2*ST_A;
        const bf16* Bl = Bh + ST_B5;

        unsigned ah[2][4], al[2][4];
        #pragma unroll
        for (int im = 0; im < 2; im++) {
            ldsm4(ah[im], &Ah[(wm*32 + im*16 + arow) * ASTR + acol]);
            ldsm4(al[im], &Al[(wm*32 + im*16 + arow) * ASTR + acol]);
        }
        #pragma unroll
        for (int jn = 0; jn < 2; jn++) {
            unsigned bh4[4], bl4[4];
            const int boff = bkrow * BSTR5 + wn*32 + jn*16 + bncol;
            ldsm4t(bh4, &Bh[boff]);
            ldsm4t(bl4, &Bl[boff]);
            #pragma unroll
            for (int im = 0; im < 2; im++) {
                mma16816(acc[im][2*jn],   ah[im], bh4[0], bh4[1]);
                mma16816(acc[im][2*jn],   al[im], bh4[0], bh4[1]);
                mma16816(acc[im][2*jn],   ah[im], bl4[0], bl4[1]);
                mma16816(acc[im][2*jn+1], ah[im], bh4[2], bh4[3]);
                mma16816(acc[im][2*jn+1], al[im], bh4[2], bh4[3]);
                mma16816(acc[im][2*jn+1], ah[im], bl4[2], bl4[3]);
            }
        }
        __syncthreads();
    }

    // staged epilogue: fragments -> smem fp32 (64x64) -> scatter
    const int r = lane >> 2, cq = (lane & 3) * 2;
    #pragma unroll
    for (int im = 0; im < 2; im++) {
        __syncthreads();
        #pragma unroll
        for (int j8 = 0; j8 < 4; j8++) {
            int col = wn*32 + j8*8 + cq;
            Cst[(wm*16 + r) * 64 + col]         = acc[im][j8][0];
            Cst[(wm*16 + r) * 64 + col + 1]     = acc[im][j8][1];
            Cst[(wm*16 + r + 8) * 64 + col]     = acc[im][j8][2];
            Cst[(wm*16 + r + 8) * 64 + col + 1] = acc[im][j8][3];
        }
        __syncthreads();

        if (m0 == 256) {
            // V block: transposed layout is n-contiguous -> keep n-order scatter
            for (int idx = tid; idx < 64*64; idx += 256) {
                int srow = idx >> 6, scol = idx & 63;
                int o = m0 + (srow >> 4) * 32 + im*16 + (srow & 15);
                int n = n0 + scol;
                float v = Cst[idx] + bias[o];
                int h = (o & 127) >> 5, d = o & 31;
                bf16 hh, ll; bsplit(v, hh, ll);
                size_t i2 = ((size_t)(b*NHEAD + h) * HD + d) * N + n;
                Vh_[i2] = hh;  Vl_[i2] = ll;
            }
        } else {
            // Q/K block: coalesced d-run writes (uint2 = 4 bf16 along d)
            const bool isQ = (m0 == 0);
            bf16* Dh = isQ ? Qh_ : Kh_;
            bf16* Dl = isQ ? Ql_ : Kl_;
            const float scale = isQ ? GAMMA_L2E : 1.0f;
            for (int idx2 = tid; idx2 < 1024; idx2 += 256) {
                int c4  = idx2 & 3;             // 4-d chunk within 16-d run
                int h   = (idx2 >> 2) & 3;      // head
                int nl  = idx2 >> 4;            // local n 0..63
                int dl0 = c4 * 4;               // within-run d offset
                int d0  = im * 16 + dl0;        // global d base
                int obase = m0 + h * 32 + im * 16 + dl0;
                bf16 hh[4], ll[4];
                #pragma unroll
                for (int j = 0; j < 4; j++) {
                    float v = (Cst[(16*h + dl0 + j) * 64 + nl] + bias[obase + j]) * scale;
                    bsplit(v, hh[j], ll[j]);
                }
                size_t base2 = ((size_t)(b*NHEAD + h) * N + (n0 + nl)) * HD + d0;
                *(uint2*)&Dh[base2] = make_uint2(pack2(hh[0],hh[1]), pack2(hh[2],hh[3]));
                *(uint2*)&Dl[base2] = make_uint2(pack2(ll[0],ll[1]), pack2(ll[2],ll[3]));
            }
        }
    }
}

// ====== proj tensor-core GEMM (validated round-14) =========================
__global__ void __launch_bounds__(256) proj_mma_kernel(
    const float* __restrict__ bpx, const float* __restrict__ Rx,
    const float* __restrict__ bpy, const float* __restrict__ Ry,
    float* __restrict__ outp)
{
    __shared__ __align__(16) char SMB[33792];
    bf16* SM = (bf16*)SMB;
    float* Cst = (float*)SMB;

    const bf16 *Wh, *Wl, *Xh, *Xl;
    const float *bias, *Res;
    float* Out;
    int N, OC, m0, n0, b;
    int blk = blockIdx.x;
    if (blk < 128) {
        N = HWY; OC = Y_CH;
        b = blk / 64; int r = blk % 64; m0 = (r % 4) * 128; n0 = (r / 4) * 64;
        Wh = g_wpyh; Wl = g_wpyl;
        Xh = g_ayh + (size_t)b * DIM * N; Xl = g_ayl + (size_t)b * DIM * N;
        bias = bpy; Res = Ry; Out = outp + (size_t)BATCH * X_CH * HWX;
    } else {
        blk -= 128;
        N = HWX; OC = X_CH;
        b = blk / 128; int r = blk % 128; m0 = (r % 2) * 128; n0 = (r / 2) * 64;
        Wh = g_wpxh; Wl = g_wpxl;
        Xh = g_axh + (size_t)b * DIM * N; Xl = g_axl + (size_t)b * DIM * N;
        bias = bpx; Res = Rx; Out = outp;
    }
    const int K = DIM;

    const int tid = threadIdx.x, lane = tid & 31;
    const int w = tid >> 5;
    const int wm = w & 3, wn = w >> 2;
    const int arow = (lane & 7) + ((lane & 8) ? 8 : 0);
    const int acol = (lane & 16) ? 8 : 0;
    const int bkrow = (lane & 7) + ((lane & 8) ? 8 : 0);
    const int bncol = (lane & 16) ? 8 : 0;

    const unsigned sbase = (unsigned)__cvta_generic_to_shared(SMB);

    auto fill = [&](int s, int kc) {
        #pragma unroll
        for (int it = 0; it < 3; it++) {
            int id = tid + it * 256;
            if (id < 512) {
                int part = id & 1, rid = id >> 1;
                int row = rid >> 1, cc = rid & 1;
                unsigned adst = sbase + (unsigned)(s*ST_TOT5 + part*ST_A + row*ASTR + cc*8) * 2;
                cpasync16(adst, (part ? Wl : Wh) + (size_t)(m0 + row) * K + kc*16 + cc*8);
            } else {
                int j = id - 512;
                int part = j & 1, rid2 = j >> 1;
                int krow = rid2 >> 3, nc = rid2 & 7;
                unsigned bdst = sbase + (unsigned)(s*ST_TOT5 + 2*ST_A + part*ST_B5 + krow*BSTR5 + nc*8) * 2;
                cpasync16(bdst, (part ? Xl : Xh) + (size_t)(kc*16 + krow) * N + n0 + nc*8);
            }
        }
        asm volatile("cp.async.commit_group;");
    };

    float acc[2][4][4] = {};
    const int nkc = K >> 4;

    fill(0, 0);
    for (int kc = 0; kc < nkc; kc++) {
        const int s = kc & 1;
        if (kc + 1 < nkc) {
            fill(s ^ 1, kc + 1);
            asm volatile("cp.async.wait_group 1;" ::: "memory");
        } else {
            asm volatile("cp.async.wait_group 0;" ::: "memory");
        }
        __syncthreads();

        const bf16* Ah = SM + s*ST_TOT5;
        const bf16* Al = Ah + ST_A;
        const bf16* Bh = SM + s*ST_TOT5 + 2*ST_A;
        const bf16* Bl = Bh + ST_B5;

        unsigned ah[2][4], al[2][4];
        #pragma unroll
        for (int im = 0; im < 2; im++) {
            ldsm4(ah[im], &Ah[(wm*32 + im*16 + arow) * ASTR + acol]);
            ldsm4(al[im], &Al[(wm*32 + im*16 + arow) * ASTR + acol]);
        }
        #pragma unroll
        for (int jn = 0; jn < 2; jn++) {
            unsigned bh4[4], bl4[4];
            const int boff = bkrow * BSTR5 + wn*32 + jn*16 + bncol;
            ldsm4t(bh4, &Bh[boff]);
            ldsm4t(bl4, &Bl[boff]);
            #pragma unroll
            for (int im = 0; im < 2; im++) {
                mma16816(acc[im][2*jn],   ah[im], bh4[0], bh4[1]);
                mma16816(acc[im][2*jn],   al[im], bh4[0], bh4[1]);
                mma16816(acc[im][2*jn],   ah[im], bl4[0], bl4[1]);
                mma16816(acc[im][2*jn+1], ah[im], bh4[2], bh4[3]);
                mma16816(acc[im][2*jn+1], al[im], bh4[2], bh4[3]);
                mma16816(acc[im][2*jn+1], ah[im], bl4[2], bl4[3]);
            }
        }
        __syncthreads();
    }

    const int r = lane >> 2, cq = (lane & 3) * 2;
    #pragma unroll
    for (int im = 0; im < 2; im++) {
        __syncthreads();
        #pragma unroll
        for (int j8 = 0; j8 < 4; j8++) {
            int col = wn*32 + j8*8 + cq;
            Cst[(wm*16 + r) * 64 + col]         = acc[im][j8][0];
            Cst[(wm*16 + r) * 64 + col + 1]     = acc[im][j8][1];
            Cst[(wm*16 + r + 8) * 64 + col]     = acc[im][j8][2];
            Cst[(wm*16 + r + 8) * 64 + col + 1] = acc[im][j8][3];
        }
        __syncthreads();
        for (int idx = tid; idx < 64*64; idx += 256) {
            int srow = idx >> 6, scol = idx & 63;
            int o = m0 + (srow >> 4) * 32 + im*16 + (srow & 15);
            int n = n0 + scol;
            size_t off = ((size_t)b * OC + o) * N + n;
            Out[off] = Cst[idx] + bias[o] + Res[off];
        }
    }
}

// ====== MMA flash attention (validated round-14: 4 warps, split-K dir1) ====
#define QSTR 40
#define VSTR 72
#define OFF_KH 0
#define OFF_KL 2560
#define OFF_VH 5120
#define OFF_VL 7424
#define STAGE_ELEMS 9728

__global__ void __launch_bounds__(128) attn_mma_kernel()
{
    __shared__ __align__(16) bf16 KV[2][STAGE_ELEMS];

    int blk = blockIdx.x;
    const bf16 *Qh, *Ql, *Kh, *Kl, *Vh, *Vl;
    bf16 *Oh_ = nullptr, *Ol_ = nullptr;
    int NQ, NK, bh, q0, kt0, sp = 0;
    bool split;
    if (blk < 512) {
        split = true;
        bh = blk >> 6;
        int r2 = blk & 63;
        q0 = (r2 >> 2) * 64;
        sp = r2 & 3;
        kt0 = sp * 16;
        NQ = HWY; NK = HWX;
        Qh=g_qyh; Ql=g_qyl; Kh=g_kxh; Kl=g_kxl; Vh=g_vxh; Vl=g_vxl;
    } else {
        split = false;
        blk -= 512;
        bh = blk >> 6; q0 = (blk & 63) * 64; kt0 = 0; NQ = HWX; NK = HWY;
        Qh=g_qxh; Ql=g_qxl; Kh=g_kyh; Kl=g_kyl; Vh=g_vyh; Vl=g_vyl;
        Oh_ = g_axh; Ol_ = g_axl;
    }
    const int nt = 16;

    const int tid = threadIdx.x, w = tid >> 5, lane = tid & 31;
    const size_t kbase = (size_t)bh * NK * HD;
    const size_t vbase = (size_t)bh * HD * NK;

    const int e0 = tid * 8, e1 = (tid + 128) * 8;
    const int ks0 = (e0 >> 5) * QSTR + (e0 & 31);
    const int ks1 = (e1 >> 5) * QSTR + (e1 & 31);
    const int vs0 = (e0 >> 6) * VSTR + (e0 & 63);
    const int vs1 = (e1 >> 6) * VSTR + (e1 & 63);
    const size_t kg0 = (size_t)(e0 >> 5) * HD + (e0 & 31);
    const size_t kg1 = (size_t)(e1 >> 5) * HD + (e1 & 31);
    const size_t vg0 = (size_t)(e0 >> 6) * NK + (e0 & 63);
    const size_t vg1 = (size_t)(e1 >> 6) * NK + (e1 & 63);

    unsigned sb0 = (unsigned)__cvta_generic_to_shared(&KV[0][0]);
    unsigned sb1 = (unsigned)__cvta_generic_to_shared(&KV[1][0]);

    {
        size_t ka = kbase + (size_t)kt0 * 64 * HD;
        size_t va = vbase + (size_t)kt0 * 64;
        cpasync16(sb0 + (OFF_KH + ks0) * 2, Kh + ka + kg0);
        cpasync16(sb0 + (OFF_KH + ks1) * 2, Kh + ka + kg1);
        cpasync16(sb0 + (OFF_KL + ks0) * 2, Kl + ka + kg0);
        cpasync16(sb0 + (OFF_KL + ks1) * 2, Kl + ka + kg1);
        cpasync16(sb0 + (OFF_VH + vs0) * 2, Vh + va + vg0);
        cpasync16(sb0 + (OFF_VH + vs1) * 2, Vh + va + vg1);
        cpasync16(sb0 + (OFF_VL + vs0) * 2, Vl + va + vg0);
        cpasync16(sb0 + (OFF_VL + vs1) * 2, Vl + va + vg1);
        asm volatile("cp.async.commit_group;");
    }

    {
        bf16* Qsh = &KV[1][0];
        bf16* Qsl = &KV[1][2560];
        const size_t qb = (size_t)bh * NQ * HD + (size_t)q0 * HD;
        #pragma unroll
        for (int it = 0; it < 2; it++) {
            int e = (tid + it * 128) * 8;
            int row = e >> 5, col = e & 31;
            *(uint4*)&Qsh[row * QSTR + col] = *(const uint4*)(Qh + qb + (size_t)row * HD + col);
            *(uint4*)&Qsl[row * QSTR + col] = *(const uint4*)(Ql + qb + (size_t)row * HD + col);
        }
    }
    __syncthreads();

    const int arow = (lane & 7) + ((lane & 8) ? 8 : 0);
    const int acol = (lane & 16) ? 8 : 0;
    const int brow = (lane & 7) + ((lane & 16) ? 8 : 0);
    const int bcol = (lane & 8) ? 8 : 0;
    unsigned qf[2][2][4];
    #pragma unroll
    for (int p = 0; p < 2; p++)
        #pragma unroll
        for (int c = 0; c < 2; c++)
            ldsm4(qf[p][c], &KV[1][p * 2560 + (w * 16 + arow) * QSTR + c * 16 + acol]);
    __syncthreads();

    float m0r = -1e30f, m1r = -1e30f, l0 = 0.f, l1 = 0.f;
    float oacc[4][4] = {};

    for (int i = 0; i < nt; i++) {
        const int s = i & 1;
        if (i + 1 < nt) {
            unsigned sb = (s ^ 1) ? sb1 : sb0;
            size_t ka = kbase + (size_t)(kt0 + i + 1) * 64 * HD;
            size_t va = vbase + (size_t)(kt0 + i + 1) * 64;
            cpasync16(sb + (OFF_KH + ks0) * 2, Kh + ka + kg0);
            cpasync16(sb + (OFF_KH + ks1) * 2, Kh + ka + kg1);
            cpasync16(sb + (OFF_KL + ks0) * 2, Kl + ka + kg0);
            cpasync16(sb + (OFF_KL + ks1) * 2, Kl + ka + kg1);
            cpasync16(sb + (OFF_VH + vs0) * 2, Vh + va + vg0);
            cpasync16(sb + (OFF_VH + vs1) * 2, Vh + va + vg1);
            cpasync16(sb + (OFF_VL + vs0) * 2, Vl + va + vg0);
            cpasync16(sb + (OFF_VL + vs1) * 2, Vl + va + vg1);
            asm volatile("cp.async.commit_group;");
            asm volatile("cp.async.wait_group 1;" ::: "memory");
        } else {
            asm volatile("cp.async.wait_group 0;" ::: "memory");
        }
        __syncthreads();

        const bf16* Ks0 = &KV[s][OFF_KH];
        const bf16* Ks1 = &KV[s][OFF_KL];
        const bf16* Vs0 = &KV[s][OFF_VH];
        const bf16* Vs1 = &KV[s][OFF_VL];

        float sreg[8][4];
        #pragma unroll
        for (int nb = 0; nb < 8; nb++)
            sreg[nb][0] = sreg[nb][1] = sreg[nb][2] = sreg[nb][3] = 0.f;

        #pragma unroll
        for (int c = 0; c < 2; c++) {
            #pragma unroll
            for (int jp = 0; jp < 4; jp++) {
                unsigned kh4[4], kl4[4];
                ldsm4(kh4, &Ks0[(jp * 16 + brow) * QSTR + c * 16 + bcol]);
                ldsm4(kl4, &Ks1[(jp * 16 + brow) * QSTR + c * 16 + bcol]);
                mma16816(sreg[2*jp],   qf[0][c], kh4[0], kh4[1]);
                mma16816(sreg[2*jp],   qf[1][c], kh4[0], kh4[1]);
                mma16816(sreg[2*jp],   qf[0][c], kl4[0], kl4[1]);
                mma16816(sreg[2*jp+1], qf[0][c], kh4[2], kh4[3]);
                mma16816(sreg[2*jp+1], qf[1][c], kh4[2], kh4[3]);
                mma16816(sreg[2*jp+1], qf[0][c], kl4[2], kl4[3]);
            }
        }

        float mx0 = sreg[0][0], mx1 = sreg[0][2];
        #pragma unroll
        for (int nb = 0; nb < 8; nb++) {
            mx0 = fmaxf(mx0, fmaxf(sreg[nb][0], sreg[nb][1]));
            mx1 = fmaxf(mx1, fmaxf(sreg[nb][2], sreg[nb][3]));
        }
        mx0 = fmaxf(mx0, __shfl_xor_sync(~0u, mx0, 1));
        mx0 = fmaxf(mx0, __shfl_xor_sync(~0u, mx0, 2));
        mx1 = fmaxf(mx1, __shfl_xor_sync(~0u, mx1, 1));
        mx1 = fmaxf(mx1, __shfl_xor_sync(~0u, mx1, 2));
        float nm0 = fmaxf(m0r, mx0), nm1 = fmaxf(m1r, mx1);
        float sc0 = exp2f(m0r - nm0), sc1 = exp2f(m1r - nm1);
        m0r = nm0; m1r = nm1;
        float rs0 = 0.f, rs1 = 0.f;
        #pragma unroll
        for (int nb = 0; nb < 8; nb++) {
            sreg[nb][0] = exp2f(sreg[nb][0] - nm0);
            sreg[nb][1] = exp2f(sreg[nb][1] - nm0);
            sreg[nb][2] = exp2f(sreg[nb][2] - nm1);
            sreg[nb][3] = exp2f(sreg[nb][3] - nm1);
            rs0 += sreg[nb][0] + sreg[nb][1];
            rs1 += sreg[nb][2] + sreg[nb][3];
        }
        rs0 += __shfl_xor_sync(~0u, rs0, 1);
        rs0 += __shfl_xor_sync(~0u, rs0, 2);
        rs1 += __shfl_xor_sync(~0u, rs1, 1);
        rs1 += __shfl_xor_sync(~0u, rs1, 2);
        l0 = l0 * sc0 + rs0;  l1 = l1 * sc1 + rs1;
        #pragma unroll
        for (int nb = 0; nb < 4; nb++) {
            oacc[nb][0] *= sc0; oacc[nb][1] *= sc0;
            oacc[nb][2] *= sc1; oacc[nb][3] *= sc1;
        }

        #pragma unroll
        for (int c = 0; c < 4; c++) {
            unsigned pah[4], pal[4];
            #pragma unroll
            for (int r4 = 0; r4 < 4; r4++) {
                int nb = 2 * c + (r4 >> 1);
                int pr = (r4 & 1) * 2;
                psplit2(sreg[nb][pr], sreg[nb][pr + 1], pah[r4], pal[r4]);
            }
            #pragma unroll
            for (int np = 0; np < 2; np++) {
                unsigned vh4[4], vl4[4];
                ldsm4(vh4, &Vs0[(np * 16 + brow) * VSTR + c * 16 + bcol]);
                ldsm4(vl4, &Vs1[(np * 16 + brow) * VSTR + c * 16 + bcol]);
                mma16816(oacc[2*np],   pah, vh4[0], vh4[1]);
                mma16816(oacc[2*np],   pal, vh4[0], vh4[1]);
                mma16816(oacc[2*np],   pah, vl4[0], vl4[1]);
                mma16816(oacc[2*np+1], pah, vh4[2], vh4[3]);
                mma16816(oacc[2*np+1], pal, vh4[2], vh4[3]);
                mma16816(oacc[2*np+1], pah, vl4[2], vl4[3]);
            }
        }
        __syncthreads();
    }

    int r = lane >> 2;
    int qg = q0 + w * 16 + r;
    if (split) {
        size_t pb = ((size_t)sp * 8 + bh) * HWY;
        #pragma unroll
        for (int nb = 0; nb < 4; nb++) {
            int d = nb * 8 + (lane & 3) * 2;
            *(float2*)&g_pacc[(pb + qg) * HD + d]     = make_float2(oacc[nb][0], oacc[nb][1]);
            *(float2*)&g_pacc[(pb + qg + 8) * HD + d] = make_float2(oacc[nb][2], oacc[nb][3]);
        }
        if ((lane & 3) == 0) {
            g_pml[pb + qg]     = make_float2(m0r, l0);
            g_pml[pb + qg + 8] = make_float2(m1r, l1);
        }
    } else {
        float inv0 = 1.f / l0, inv1 = 1.f / l1;
        size_t ob = (size_t)bh * HD * NQ;
        #pragma unroll
        for (int nb = 0; nb < 4; nb++) {
            int d = nb * 8 + (lane & 3) * 2;
            bf16 hh, ll;
            bsplit(oacc[nb][0] * inv0, hh, ll);
            Oh_[ob + (size_t)d * NQ + qg] = hh;       Ol_[ob + (size_t)d * NQ + qg] = ll;
            bsplit(oacc[nb][1] * inv0, hh, ll);
            Oh_[ob + (size_t)(d+1) * NQ + qg] = hh;   Ol_[ob + (size_t)(d+1) * NQ + qg] = ll;
            bsplit(oacc[nb][2] * inv1, hh, ll);
            Oh_[ob + (size_t)d * NQ + qg + 8] = hh;   Ol_[ob + (size_t)d * NQ + qg + 8] = ll;
            bsplit(oacc[nb][3] * inv1, hh, ll);
            Oh_[ob + (size_t)(d+1) * NQ + qg + 8] = hh; Ol_[ob + (size_t)(d+1) * NQ + qg + 8] = ll;
        }
    }
}

// ====== combine split-K partials (validated round-14) ======================
__global__ void __launch_bounds__(128) attn_combine_kernel()
{
    int t = blockIdx.x * 128 + threadIdx.x;
    int bh = t >> 10, q = t & 1023;
    float2 ml[4];
    float M = -1e30f;
    #pragma unroll
    for (int s = 0; s < 4; s++) {
        ml[s] = g_pml[((size_t)s * 8 + bh) * HWY + q];
        M = fmaxf(M, ml[s].x);
    }
    float wgt[4], L = 0.f;
    #pragma unroll
    for (int s = 0; s < 4; s++) {
        wgt[s] = exp2f(ml[s].x - M);
        L += wgt[s] * ml[s].y;
    }
    float invL = 1.f / L;
    size_t ob = (size_t)bh * HD * HWY;
    #pragma unroll
    for (int d4 = 0; d4 < HD; d4 += 4) {
        float4 o = make_float4(0.f, 0.f, 0.f, 0.f);
        #pragma unroll
        for (int s = 0; s < 4; s++) {
            const float* a = g_pacc + (((size_t)s * 8 + bh) * HWY + q) * HD;
            float4 v = *(const float4*)(a + d4);
            o.x += wgt[s] * v.x;  o.y += wgt[s] * v.y;
            o.z += wgt[s] * v.z;  o.w += wgt[s] * v.w;
        }
        float vals[4] = {o.x * invL, o.y * invL, o.z * invL, o.w * invL};
        #pragma unroll
        for (int j = 0; j < 4; j++) {
            bf16 hh, ll; bsplit(vals[j], hh, ll);
            g_ayh[ob + (size_t)(d4 + j) * HWY + q] = hh;
            g_ayl[ob + (size_t)(d4 + j) * HWY + q] = ll;
        }
    }
}

// ============================== launcher ==================================
extern "C" void kernel_launch(void* const* d_in, const int* in_sizes, int n_in,
                              void* d_out, int out_size)
{
    (void)out_size;
    const float *x=0, *y=0, *wxq=0, *bxq=0, *wyq=0, *byq=0,
                *wpx=0, *bpx=0, *wpy=0, *bpy=0;
    for (int i = 0; i < n_in; i++) {
        const float* p = (const float*)d_in[i];
        switch (in_sizes[i]) {
            case 2097152: x = p;   break;
            case 1048576: y = p;   break;
            case 98304:   wxq = p; break;
            case 196608:  wyq = p; break;
            case 32768:   wpx = p; break;
            case 65536:   wpy = p; break;
            case 256:     bpx = p; break;
            case 512:     bpy = p; break;
            case 384:     if (!bxq) bxq = p; else byq = p; break;
            default: break;
        }
    }
    float* out = (float*)d_out;

    split_w_kernel<<<384, 256>>>(wxq, wyq, wpx, wpy);
    presplit_x_kernel<<<3072, 256>>>(x, y);
    qkv_mma5_kernel<<<480, 256>>>(bxq, byq);
    attn_mma_kernel<<<1024, 128>>>();
    attn_combine_kernel<<<64, 128>>>();
    proj_mma_kernel<<<384, 256>>>(bpx, x, bpy, y, out);
}